// round 9
// baseline (speedup 1.0000x reference)
#include <cuda_runtime.h>
#include <cuda_bf16.h>
#include <math.h>
#include <stdint.h>

#define BSZ  256
#define HDIM 1024
#define DDIM 256
#define TLEN 64
#define FC1N 1024
#define FC2N 512

// ============================ PTX helpers ====================================
__device__ __forceinline__ uint32_t smem_u32(const void* p) {
    uint32_t a;
    asm("{ .reg .u64 t; cvta.to.shared.u64 t, %1; cvt.u32.u64 %0, t; }" : "=r"(a) : "l"(p));
    return a;
}
__device__ __forceinline__ void ldmx4(uint32_t* r, uint32_t addr) {
    asm volatile("ldmatrix.sync.aligned.m8n8.x4.shared.b16 {%0,%1,%2,%3}, [%4];"
        : "=r"(r[0]), "=r"(r[1]), "=r"(r[2]), "=r"(r[3]) : "r"(addr));
}
__device__ __forceinline__ void mma_bf16(float* d, const uint32_t* a, const uint32_t* b) {
    asm volatile("mma.sync.aligned.m16n8k16.row.col.f32.bf16.bf16.f32 "
        "{%0,%1,%2,%3}, {%4,%5,%6,%7}, {%8,%9}, {%0,%1,%2,%3};"
        : "+f"(d[0]), "+f"(d[1]), "+f"(d[2]), "+f"(d[3])
        : "r"(a[0]), "r"(a[1]), "r"(a[2]), "r"(a[3]), "r"(b[0]), "r"(b[1]));
}
__device__ __forceinline__ void cpasync16(uint32_t dst, const void* src) {
    asm volatile("cp.async.cg.shared.global [%0], [%1], 16;" :: "r"(dst), "l"(src));
}
#define CP_COMMIT asm volatile("cp.async.commit_group;" ::: "memory")
#define CP_WAIT0  asm volatile("cp.async.wait_group 0;" ::: "memory")

// ====================== persistent device scratch ============================
__device__ float g_h0f[BSZ * HDIM];
__device__ float g_h1f[BSZ * HDIM];
__device__ float g_giA[BSZ * 3 * HDIM], g_giB[BSZ * 3 * HDIM];
__device__ float g_ghA[BSZ * 3 * HDIM], g_ghB[BSZ * 3 * HDIM];
__device__ float g_z1A[BSZ * FC1N], g_z1B[BSZ * FC1N];
__device__ float g_z2A[BSZ * FC2N], g_z2B[BSZ * FC2N];
__device__ float g_z3A[BSZ * DDIM], g_z3B[BSZ * DDIM];
__device__ __nv_bfloat16 g_out_hi[BSZ * DDIM],  g_out_lo[BSZ * DDIM];
__device__ __nv_bfloat16 g_h0_hi [BSZ * HDIM],  g_h0_lo [BSZ * HDIM];
__device__ __nv_bfloat16 g_h1_hi [BSZ * HDIM],  g_h1_lo [BSZ * HDIM];
__device__ __nv_bfloat16 g_z1_hi [BSZ * FC1N],  g_z1_lo [BSZ * FC1N];
__device__ __nv_bfloat16 g_z2_hi [BSZ * FC2N],  g_z2_lo [BSZ * FC2N];
__device__ __nv_bfloat16 g_wih0_hi[3*HDIM*DDIM], g_wih0_lo[3*HDIM*DDIM];
__device__ __nv_bfloat16 g_whh0_hi[3*HDIM*HDIM], g_whh0_lo[3*HDIM*HDIM];
__device__ __nv_bfloat16 g_wih1_hi[3*HDIM*HDIM], g_wih1_lo[3*HDIM*HDIM];
__device__ __nv_bfloat16 g_whh1_hi[3*HDIM*HDIM], g_whh1_lo[3*HDIM*HDIM];
__device__ __nv_bfloat16 g_fc1_hi[FC1N*HDIM],    g_fc1_lo[FC1N*HDIM];
__device__ __nv_bfloat16 g_fc2_hi[FC2N*FC1N],    g_fc2_lo[FC2N*FC1N];
__device__ __nv_bfloat16 g_fc3_hi[DDIM*FC2N],    g_fc3_lo[DDIM*FC2N];

// grid barrier state
__device__ unsigned g_arrive = 0;
__device__ unsigned g_gen    = 0;

// ============================ small kernels ==================================
__global__ void split_kernel(const float* __restrict__ x,
                             __nv_bfloat16* __restrict__ hi,
                             __nv_bfloat16* __restrict__ lo, int n) {
    int i = blockIdx.x * blockDim.x + threadIdx.x;
    if (i < n) {
        float v = x[i];
        __nv_bfloat16 h = __float2bfloat16(v);
        hi[i] = h;
        lo[i] = __float2bfloat16(v - __bfloat162float(h));
    }
}

__global__ void init_kernel(const float* __restrict__ hidden) {
    int i = blockIdx.x * blockDim.x + threadIdx.x;
    if (i < BSZ * HDIM) {
        float v0 = hidden[i];
        float v1 = hidden[BSZ * HDIM + i];
        g_h0f[i] = v0; g_h1f[i] = v1;
        __nv_bfloat16 h0 = __float2bfloat16(v0);
        __nv_bfloat16 h1 = __float2bfloat16(v1);
        g_h0_hi[i] = h0; g_h0_lo[i] = __float2bfloat16(v0 - __bfloat162float(h0));
        g_h1_hi[i] = h1; g_h1_lo[i] = __float2bfloat16(v1 - __bfloat162float(h1));
    }
    if (i < BSZ * DDIM) {
        g_out_hi[i] = __float2bfloat16(0.0f);
        g_out_lo[i] = __float2bfloat16(0.0f);
    }
}

// ============================ grid barrier ===================================
__device__ __forceinline__ void grid_sync() {
    __threadfence();
    __syncthreads();
    if (threadIdx.x == 0) {
        unsigned gen = *(volatile unsigned*)&g_gen;
        if (atomicAdd(&g_arrive, 1u) == gridDim.x - 1u) {
            atomicExch(&g_arrive, 0u);
            __threadfence();
            atomicAdd(&g_gen, 1u);
        } else {
            while (*(volatile unsigned*)&g_gen == gen) __nanosleep(32);
        }
    }
    __syncthreads();
}

// ===================== mma.sync split-bf16 GEMM tile =========================
template <int BM, int WM>
__device__ __forceinline__ void gemm_tile(
    const __nv_bfloat16* __restrict__ Ahi, const __nv_bfloat16* __restrict__ Alo,
    const __nv_bfloat16* __restrict__ Bhi, const __nv_bfloat16* __restrict__ Blo,
    float* __restrict__ C, int K, int kOff, int kLen, int N,
    int row0, int col0, uint32_t sb)
{
    constexpr int BN = 64, WN = 32;
    constexpr int PITCH = 80;
    constexpr int A_SZ  = BM * PITCH;
    constexpr int B_SZ  = BN * PITCH;
    constexpr int STAGE = 2 * A_SZ + 2 * B_SZ;
    constexpr int WARPS_N = BN / WN;
    constexpr int MT  = WM / 16;
    constexpr int NT  = WN / 8;
    constexpr int NT2 = WN / 16;

    const int tid  = threadIdx.x;
    const int wid  = tid >> 5;
    const int lane = tid & 31;
    const int wm0  = (wid / WARPS_N) * WM;
    const int wn0  = (wid % WARPS_N) * WN;
    const int NC   = kLen >> 5;

    float acc[MT][NT][4] = {};

    auto copy_chunk = [&](int c, int buf) {
        const uint32_t base = sb + buf * STAGE;
        const int kb = kOff + (c << 5);
        #pragma unroll
        for (int i = tid; i < BM * 4; i += 256) {
            int r = i >> 2, q = i & 3;
            size_t g = (size_t)(row0 + r) * K + kb + q * 8;
            uint32_t d = base + r * PITCH + q * 16;
            cpasync16(d,        Ahi + g);
            cpasync16(d + A_SZ, Alo + g);
        }
        #pragma unroll
        for (int i = tid; i < BN * 4; i += 256) {
            int r = i >> 2, q = i & 3;
            size_t g = (size_t)(col0 + r) * K + kb + q * 8;
            uint32_t d = base + 2 * A_SZ + r * PITCH + q * 16;
            cpasync16(d,        Bhi + g);
            cpasync16(d + B_SZ, Blo + g);
        }
    };

    copy_chunk(0, 0);
    CP_COMMIT;

    int buf = 0;
    for (int c = 0; c < NC; c++) {
        CP_WAIT0;
        __syncthreads();
        if (c + 1 < NC) { copy_chunk(c + 1, buf ^ 1); CP_COMMIT; }

        const uint32_t aBase = sb + buf * STAGE;
        const uint32_t bBase = aBase + 2 * A_SZ;

        #pragma unroll
        for (int ks = 0; ks < 2; ks++) {
            uint32_t ah[MT][4], al[MT][4], bh[NT2][4], bl[NT2][4];
            #pragma unroll
            for (int mt = 0; mt < MT; mt++) {
                uint32_t ad = aBase + (wm0 + mt * 16 + (lane & 15)) * PITCH
                            + ks * 32 + ((lane >> 4) << 4);
                ldmx4(ah[mt], ad);
                ldmx4(al[mt], ad + A_SZ);
            }
            #pragma unroll
            for (int n2 = 0; n2 < NT2; n2++) {
                int nr = wn0 + n2 * 16 + (lane & 7) + ((lane & 16) ? 8 : 0);
                uint32_t bd = bBase + nr * PITCH + ks * 32 + ((lane & 8) ? 16 : 0);
                ldmx4(bh[n2], bd);
                ldmx4(bl[n2], bd + B_SZ);
            }
            #pragma unroll
            for (int mt = 0; mt < MT; mt++)
                #pragma unroll
                for (int nt = 0; nt < NT; nt++) {
                    const uint32_t* bph = &bh[nt >> 1][(nt & 1) * 2];
                    const uint32_t* bpl = &bl[nt >> 1][(nt & 1) * 2];
                    mma_bf16(acc[mt][nt], ah[mt], bph);
                    mma_bf16(acc[mt][nt], ah[mt], bpl);
                    mma_bf16(acc[mt][nt], al[mt], bph);
                }
        }
        __syncthreads();
        buf ^= 1;
    }

    #pragma unroll
    for (int mt = 0; mt < MT; mt++) {
        int r0 = row0 + wm0 + mt * 16 + (lane >> 2);
        #pragma unroll
        for (int nt = 0; nt < NT; nt++) {
            int cc = col0 + wn0 + nt * 8 + (lane & 3) * 2;
            float2 v0 = { acc[mt][nt][0], acc[mt][nt][1] };
            float2 v1 = { acc[mt][nt][2], acc[mt][nt][3] };
            *(float2*)(C + (size_t)r0 * N + cc)       = v0;
            *(float2*)(C + (size_t)(r0 + 8) * N + cc) = v1;
        }
    }
}

// ============================ phase helpers ==================================
__device__ __forceinline__ void layer_gemm_phase(int layer, uint32_t sb)
{
    for (int l = blockIdx.x; l < 384; l += gridDim.x) {
        int z, r;
        if (layer == 0) {   // big-K (gh) tiles first for balance
            if (l < 96)       { z = 2; r = l; }
            else if (l < 192) { z = 3; r = l - 96; }
            else if (l < 288) { z = 0; r = l - 192; }
            else              { z = 1; r = l - 288; }
        } else { z = l / 96; r = l % 96; }

        const __nv_bfloat16 *Ahi, *Alo, *Bhi, *Blo;
        float* C; int K, kOff, kLen;
        if (layer == 0) {
            switch (z) {
            case 0: Ahi=g_out_hi; Alo=g_out_lo; Bhi=g_wih0_hi; Blo=g_wih0_lo;
                    C=g_giA; K=DDIM; kOff=0;   kLen=128; break;
            case 1: Ahi=g_out_hi; Alo=g_out_lo; Bhi=g_wih0_hi; Blo=g_wih0_lo;
                    C=g_giB; K=DDIM; kOff=128; kLen=128; break;
            case 2: Ahi=g_h0_hi;  Alo=g_h0_lo;  Bhi=g_whh0_hi; Blo=g_whh0_lo;
                    C=g_ghA; K=HDIM; kOff=0;   kLen=512; break;
            default:Ahi=g_h0_hi;  Alo=g_h0_lo;  Bhi=g_whh0_hi; Blo=g_whh0_lo;
                    C=g_ghB; K=HDIM; kOff=512; kLen=512; break;
            }
        } else {
            switch (z) {
            case 0: Ahi=g_h0_hi; Alo=g_h0_lo; Bhi=g_wih1_hi; Blo=g_wih1_lo;
                    C=g_giA; K=HDIM; kOff=0;   kLen=512; break;
            case 1: Ahi=g_h0_hi; Alo=g_h0_lo; Bhi=g_wih1_hi; Blo=g_wih1_lo;
                    C=g_giB; K=HDIM; kOff=512; kLen=512; break;
            case 2: Ahi=g_h1_hi; Alo=g_h1_lo; Bhi=g_whh1_hi; Blo=g_whh1_lo;
                    C=g_ghA; K=HDIM; kOff=0;   kLen=512; break;
            default:Ahi=g_h1_hi; Alo=g_h1_lo; Bhi=g_whh1_hi; Blo=g_whh1_lo;
                    C=g_ghB; K=HDIM; kOff=512; kLen=512; break;
            }
        }
        int tx = r % 48, ty = r / 48;
        gemm_tile<128, 32>(Ahi, Alo, Bhi, Blo, C, K, kOff, kLen, 3 * HDIM,
                           ty * 128, tx * 64, sb);
    }
}

__device__ __forceinline__ void fc_gemm_phase(
    const __nv_bfloat16* Ahi, const __nv_bfloat16* Alo,
    const __nv_bfloat16* Bhi, const __nv_bfloat16* Blo,
    float* CA, float* CB, int K, int kHalf, int N, int ntiles, uint32_t sb)
{
    const int half = ntiles >> 1;
    const int xw = N / 64;
    for (int l = blockIdx.x; l < ntiles; l += gridDim.x) {
        int z = (l >= half) ? 1 : 0;
        int r = z ? l - half : l;
        int tx = r % xw, ty = r / xw;
        gemm_tile<64, 16>(Ahi, Alo, Bhi, Blo, z ? CB : CA, K, z ? kHalf : 0,
                          kHalf, N, ty * 64, tx * 64, sb);
    }
}

__device__ __forceinline__ float sigmoidf_(float x) { return 1.0f / (1.0f + expf(-x)); }

__device__ __forceinline__ void gate_phase(
    const float4* giA, const float4* giB, const float4* ghA, const float4* ghB,
    const float4* bih, const float4* bhh,
    float4* h, __nv_bfloat16* hhi, __nv_bfloat16* hlo)
{
    const int total = BSZ * HDIM / 4;
    for (int idx = blockIdx.x * blockDim.x + threadIdx.x; idx < total;
         idx += gridDim.x * blockDim.x) {
        int b = idx >> 8;
        int j = idx & 255;
        size_t o = (size_t)b * 768;
        float4 ir4, iz4, in4, hr4, hz4, hn4;
        {
            float4 a, c, bb;
            a = __ldcg(giA + o + j);       c = __ldcg(giB + o + j);       bb = bih[j];
            ir4 = make_float4(a.x+c.x+bb.x, a.y+c.y+bb.y, a.z+c.z+bb.z, a.w+c.w+bb.w);
            a = __ldcg(giA + o + 256 + j); c = __ldcg(giB + o + 256 + j); bb = bih[256 + j];
            iz4 = make_float4(a.x+c.x+bb.x, a.y+c.y+bb.y, a.z+c.z+bb.z, a.w+c.w+bb.w);
            a = __ldcg(giA + o + 512 + j); c = __ldcg(giB + o + 512 + j); bb = bih[512 + j];
            in4 = make_float4(a.x+c.x+bb.x, a.y+c.y+bb.y, a.z+c.z+bb.z, a.w+c.w+bb.w);
            a = __ldcg(ghA + o + j);       c = __ldcg(ghB + o + j);       bb = bhh[j];
            hr4 = make_float4(a.x+c.x+bb.x, a.y+c.y+bb.y, a.z+c.z+bb.z, a.w+c.w+bb.w);
            a = __ldcg(ghA + o + 256 + j); c = __ldcg(ghB + o + 256 + j); bb = bhh[256 + j];
            hz4 = make_float4(a.x+c.x+bb.x, a.y+c.y+bb.y, a.z+c.z+bb.z, a.w+c.w+bb.w);
            a = __ldcg(ghA + o + 512 + j); c = __ldcg(ghB + o + 512 + j); bb = bhh[512 + j];
            hn4 = make_float4(a.x+c.x+bb.x, a.y+c.y+bb.y, a.z+c.z+bb.z, a.w+c.w+bb.w);
        }
        float4 hv = h[idx];
        float irA[4] = {ir4.x, ir4.y, ir4.z, ir4.w}, izA[4] = {iz4.x, iz4.y, iz4.z, iz4.w};
        float inA[4] = {in4.x, in4.y, in4.z, in4.w};
        float hrA[4] = {hr4.x, hr4.y, hr4.z, hr4.w}, hzA[4] = {hz4.x, hz4.y, hz4.z, hz4.w};
        float hnA[4] = {hn4.x, hn4.y, hn4.z, hn4.w};
        float hvA[4] = {hv.x, hv.y, hv.z, hv.w};
        float out[4];
        #pragma unroll
        for (int k = 0; k < 4; k++) {
            float r = sigmoidf_(irA[k] + hrA[k]);
            float z = sigmoidf_(izA[k] + hzA[k]);
            float n = tanhf(inA[k] + r * hnA[k]);
            out[k] = (1.0f - z) * n + z * hvA[k];
        }
        h[idx] = make_float4(out[0], out[1], out[2], out[3]);
        int base = idx * 4;
        #pragma unroll
        for (int k = 0; k < 4; k++) {
            __nv_bfloat16 hb = __float2bfloat16(out[k]);
            hhi[base + k] = hb;
            hlo[base + k] = __float2bfloat16(out[k] - __bfloat162float(hb));
        }
    }
}

template <int N>
__device__ __forceinline__ void ln_phase(
    const float* xa, const float* xb, const float* fcb,
    const float* g, const float* b,
    __nv_bfloat16* hi, __nv_bfloat16* lo)
{
    __shared__ float sv[FC1N];
    __shared__ float rs[256], rs2[256];
    const int tid = threadIdx.x;
    for (int row = blockIdx.x; row < BSZ; row += gridDim.x) {
        float s = 0.0f, s2 = 0.0f;
        #pragma unroll
        for (int j = tid; j < N; j += 256) {
            float v = __ldcg(xa + (size_t)row * N + j)
                    + __ldcg(xb + (size_t)row * N + j) + fcb[j];
            sv[j] = v; s += v; s2 += v * v;
        }
        rs[tid] = s; rs2[tid] = s2;
        __syncthreads();
        #pragma unroll
        for (int o = 128; o > 0; o >>= 1) {
            if (tid < o) { rs[tid] += rs[tid + o]; rs2[tid] += rs2[tid + o]; }
            __syncthreads();
        }
        float mu  = rs[0]  * (1.0f / N);
        float var = rs2[0] * (1.0f / N) - mu * mu;
        float inv = rsqrtf(var + 1e-5f);
        #pragma unroll
        for (int j = tid; j < N; j += 256) {
            float v = (sv[j] - mu) * inv * g[j] + b[j];
            float gv = 0.5f * v * (1.0f + erff(v * 0.70710678118654752f));
            __nv_bfloat16 hb = __float2bfloat16(gv);
            hi[(size_t)row * N + j] = hb;
            lo[(size_t)row * N + j] = __float2bfloat16(gv - __bfloat162float(hb));
        }
        __syncthreads();
    }
}

__device__ __forceinline__ void softmax_phase(
    const float* za, const float* zb, const float* fcb,
    __nv_bfloat16* ohi, __nv_bfloat16* olo, float* dst, int t)
{
    __shared__ float red[256];
    const int j = threadIdx.x;
    for (int b = blockIdx.x; b < BSZ; b += gridDim.x) {
        float v = __ldcg(za + (size_t)b * DDIM + j)
                + __ldcg(zb + (size_t)b * DDIM + j) + fcb[j];
        red[j] = v;
        __syncthreads();
        #pragma unroll
        for (int o = 128; o > 0; o >>= 1) {
            if (j < o) red[j] = fmaxf(red[j], red[j + o]);
            __syncthreads();
        }
        float m = red[0];
        __syncthreads();
        float e = expf(v - m);
        red[j] = e;
        __syncthreads();
        #pragma unroll
        for (int o = 128; o > 0; o >>= 1) {
            if (j < o) red[j] += red[j + o];
            __syncthreads();
        }
        float p = e / red[0];
        __nv_bfloat16 hb = __float2bfloat16(p);
        ohi[(size_t)b * DDIM + j] = hb;
        olo[(size_t)b * DDIM + j] = __float2bfloat16(p - __bfloat162float(hb));
        dst[((size_t)b * TLEN + t) * DDIM + j] = p;
        __syncthreads();
    }
}

// ============================ persistent kernel ==============================
struct Params {
    const float *bih0, *bhh0, *bih1, *bhh1;
    const float *fc1b, *ln1g, *ln1b, *fc2b, *ln2g, *ln2b, *fc3b;
    float* out;
};

#define SMEM_DYN (2 * (2 * 128 * 80 + 2 * 64 * 80))   // 61440

__global__ __launch_bounds__(256, 2) void decoder_kernel(Params P)
{
    extern __shared__ char smem[];
    const uint32_t sb = smem_u32(smem);

    for (int t = 0; t < TLEN; t++) {
        layer_gemm_phase(0, sb);
        grid_sync();
        gate_phase((const float4*)g_giA, (const float4*)g_giB,
                   (const float4*)g_ghA, (const float4*)g_ghB,
                   (const float4*)P.bih0, (const float4*)P.bhh0,
                   (float4*)g_h0f, g_h0_hi, g_h0_lo);
        grid_sync();
        layer_gemm_phase(1, sb);
        grid_sync();
        gate_phase((const float4*)g_giA, (const float4*)g_giB,
                   (const float4*)g_ghA, (const float4*)g_ghB,
                   (const float4*)P.bih1, (const float4*)P.bhh1,
                   (float4*)g_h1f, g_h1_hi, g_h1_lo);
        grid_sync();
        fc_gemm_phase(g_h1_hi, g_h1_lo, g_fc1_hi, g_fc1_lo,
                      g_z1A, g_z1B, HDIM, 512, FC1N, 128, sb);
        grid_sync();
        ln_phase<FC1N>(g_z1A, g_z1B, P.fc1b, P.ln1g, P.ln1b, g_z1_hi, g_z1_lo);
        grid_sync();
        fc_gemm_phase(g_z1_hi, g_z1_lo, g_fc2_hi, g_fc2_lo,
                      g_z2A, g_z2B, FC1N, 512, FC2N, 64, sb);
        grid_sync();
        ln_phase<FC2N>(g_z2A, g_z2B, P.fc2b, P.ln2g, P.ln2b, g_z2_hi, g_z2_lo);
        grid_sync();
        fc_gemm_phase(g_z2_hi, g_z2_lo, g_fc3_hi, g_fc3_lo,
                      g_z3A, g_z3B, FC2N, 256, DDIM, 32, sb);
        grid_sync();
        softmax_phase(g_z3A, g_z3B, P.fc3b, g_out_hi, g_out_lo, P.out, t);
        grid_sync();
    }
}

// ============================ host side ======================================
extern "C" void kernel_launch(void* const* d_in, const int* in_sizes, int n_in,
                              void* d_out, int out_size)
{
    const float* hidden = (const float*)d_in[0];
    const float* W_ih0  = (const float*)d_in[1];
    const float* W_hh0  = (const float*)d_in[2];
    const float* b_ih0  = (const float*)d_in[3];
    const float* b_hh0  = (const float*)d_in[4];
    const float* W_ih1  = (const float*)d_in[5];
    const float* W_hh1  = (const float*)d_in[6];
    const float* b_ih1  = (const float*)d_in[7];
    const float* b_hh1  = (const float*)d_in[8];
    const float* fc1_w  = (const float*)d_in[9];
    const float* fc1_b  = (const float*)d_in[10];
    const float* ln1_g  = (const float*)d_in[11];
    const float* ln1_b  = (const float*)d_in[12];
    const float* fc2_w  = (const float*)d_in[13];
    const float* fc2_b  = (const float*)d_in[14];
    const float* ln2_g  = (const float*)d_in[15];
    const float* ln2_b  = (const float*)d_in[16];
    const float* fc3_w  = (const float*)d_in[17];
    const float* fc3_b  = (const float*)d_in[18];
    float* out = (float*)d_out;

    cudaFuncSetAttribute(decoder_kernel,
                         cudaFuncAttributeMaxDynamicSharedMemorySize, SMEM_DYN);

    __nv_bfloat16 *wih0h, *wih0l, *whh0h, *whh0l, *wih1h, *wih1l, *whh1h, *whh1l;
    __nv_bfloat16 *f1h, *f1l, *f2h, *f2l, *f3h, *f3l;
    cudaGetSymbolAddress((void**)&wih0h, g_wih0_hi); cudaGetSymbolAddress((void**)&wih0l, g_wih0_lo);
    cudaGetSymbolAddress((void**)&whh0h, g_whh0_hi); cudaGetSymbolAddress((void**)&whh0l, g_whh0_lo);
    cudaGetSymbolAddress((void**)&wih1h, g_wih1_hi); cudaGetSymbolAddress((void**)&wih1l, g_wih1_lo);
    cudaGetSymbolAddress((void**)&whh1h, g_whh1_hi); cudaGetSymbolAddress((void**)&whh1l, g_whh1_lo);
    cudaGetSymbolAddress((void**)&f1h, g_fc1_hi); cudaGetSymbolAddress((void**)&f1l, g_fc1_lo);
    cudaGetSymbolAddress((void**)&f2h, g_fc2_hi); cudaGetSymbolAddress((void**)&f2l, g_fc2_lo);
    cudaGetSymbolAddress((void**)&f3h, g_fc3_hi); cudaGetSymbolAddress((void**)&f3l, g_fc3_lo);

    auto split = [](const float* src, __nv_bfloat16* hi, __nv_bfloat16* lo, int n) {
        split_kernel<<<n / 256, 256>>>(src, hi, lo, n);
    };
    split(W_ih0, wih0h, wih0l, 3 * HDIM * DDIM);
    split(W_hh0, whh0h, whh0l, 3 * HDIM * HDIM);
    split(W_ih1, wih1h, wih1l, 3 * HDIM * HDIM);
    split(W_hh1, whh1h, whh1l, 3 * HDIM * HDIM);
    split(fc1_w, f1h, f1l, FC1N * HDIM);
    split(fc2_w, f2h, f2l, FC2N * FC1N);
    split(fc3_w, f3h, f3l, DDIM * FC2N);

    init_kernel<<<(BSZ * HDIM + 255) / 256, 256>>>(hidden);

    Params P;
    P.bih0 = b_ih0; P.bhh0 = b_hh0; P.bih1 = b_ih1; P.bhh1 = b_hh1;
    P.fc1b = fc1_b; P.ln1g = ln1_g; P.ln1b = ln1_b;
    P.fc2b = fc2_b; P.ln2g = ln2_g; P.ln2b = ln2_b;
    P.fc3b = fc3_b; P.out = out;

    decoder_kernel<<<296, 256, SMEM_DYN>>>(P);
}

// round 12
// speedup vs baseline: 1.0157x; 1.0157x over previous
#include <cuda_runtime.h>
#include <cuda_bf16.h>
#include <math.h>
#include <stdint.h>

#define BSZ  256
#define HDIM 1024
#define DDIM 256
#define TLEN 64
#define FC1N 1024
#define FC2N 512

// ============================ PTX helpers ====================================
__device__ __forceinline__ uint32_t smem_u32(const void* p) {
    uint32_t a;
    asm("{ .reg .u64 t; cvta.to.shared.u64 t, %1; cvt.u32.u64 %0, t; }" : "=r"(a) : "l"(p));
    return a;
}
__device__ __forceinline__ void ldmx4(uint32_t* r, uint32_t addr) {
    asm volatile("ldmatrix.sync.aligned.m8n8.x4.shared.b16 {%0,%1,%2,%3}, [%4];"
        : "=r"(r[0]), "=r"(r[1]), "=r"(r[2]), "=r"(r[3]) : "r"(addr));
}
__device__ __forceinline__ void mma_bf16(float* d, const uint32_t* a, const uint32_t* b) {
    asm volatile("mma.sync.aligned.m16n8k16.row.col.f32.bf16.bf16.f32 "
        "{%0,%1,%2,%3}, {%4,%5,%6,%7}, {%8,%9}, {%0,%1,%2,%3};"
        : "+f"(d[0]), "+f"(d[1]), "+f"(d[2]), "+f"(d[3])
        : "r"(a[0]), "r"(a[1]), "r"(a[2]), "r"(a[3]), "r"(b[0]), "r"(b[1]));
}
__device__ __forceinline__ void cpasync16(uint32_t dst, const void* src) {
    asm volatile("cp.async.cg.shared.global [%0], [%1], 16;" :: "r"(dst), "l"(src));
}
#define CP_COMMIT asm volatile("cp.async.commit_group;" ::: "memory")
#define CP_WAIT0  asm volatile("cp.async.wait_group 0;" ::: "memory")
#define CP_WAIT1  asm volatile("cp.async.wait_group 1;" ::: "memory")

// ====================== persistent device scratch ============================
__device__ float g_h0f[BSZ * HDIM];
__device__ float g_h1f[BSZ * HDIM];
__device__ float g_giA[BSZ * 3 * HDIM], g_giB[BSZ * 3 * HDIM];
__device__ float g_ghA[BSZ * 3 * HDIM], g_ghB[BSZ * 3 * HDIM];
__device__ float g_z1A[BSZ * FC1N], g_z1B[BSZ * FC1N];
__device__ float g_z2A[BSZ * FC2N], g_z2B[BSZ * FC2N];
__device__ float g_z3A[BSZ * DDIM], g_z3B[BSZ * DDIM];
__device__ __nv_bfloat16 g_out_hi[BSZ * DDIM],  g_out_lo[BSZ * DDIM];
__device__ __nv_bfloat16 g_h0_hi [BSZ * HDIM],  g_h0_lo [BSZ * HDIM];
__device__ __nv_bfloat16 g_h1_hi [BSZ * HDIM],  g_h1_lo [BSZ * HDIM];
__device__ __nv_bfloat16 g_z1_hi [BSZ * FC1N],  g_z1_lo [BSZ * FC1N];
__device__ __nv_bfloat16 g_z2_hi [BSZ * FC2N],  g_z2_lo [BSZ * FC2N];
__device__ __nv_bfloat16 g_wih0_hi[3*HDIM*DDIM], g_wih0_lo[3*HDIM*DDIM];
__device__ __nv_bfloat16 g_whh0_hi[3*HDIM*HDIM], g_whh0_lo[3*HDIM*HDIM];
__device__ __nv_bfloat16 g_wih1_hi[3*HDIM*HDIM], g_wih1_lo[3*HDIM*HDIM];
__device__ __nv_bfloat16 g_whh1_hi[3*HDIM*HDIM], g_whh1_lo[3*HDIM*HDIM];
__device__ __nv_bfloat16 g_fc1_hi[FC1N*HDIM],    g_fc1_lo[FC1N*HDIM];
__device__ __nv_bfloat16 g_fc2_hi[FC2N*FC1N],    g_fc2_lo[FC2N*FC1N];
__device__ __nv_bfloat16 g_fc3_hi[DDIM*FC2N],    g_fc3_lo[DDIM*FC2N];

// ============================ setup kernels ==================================
struct SplitJob { const float* src; __nv_bfloat16* hi; __nv_bfloat16* lo; int n; };
struct SplitJobs { SplitJob j[4]; int cnt; };

__global__ void split_multi(SplitJobs J) {
    for (int jb = 0; jb < J.cnt; jb++) {
        const float* __restrict__ src = J.j[jb].src;
        __nv_bfloat16* __restrict__ hi = J.j[jb].hi;
        __nv_bfloat16* __restrict__ lo = J.j[jb].lo;
        const int n = J.j[jb].n;
        for (int i = blockIdx.x * blockDim.x + threadIdx.x; i < n;
             i += gridDim.x * blockDim.x) {
            float v = src[i];
            __nv_bfloat16 h = __float2bfloat16(v);
            hi[i] = h;
            lo[i] = __float2bfloat16(v - __bfloat162float(h));
        }
    }
}

__global__ void init_kernel(const float* __restrict__ hidden) {
    int i = blockIdx.x * blockDim.x + threadIdx.x;
    if (i < BSZ * HDIM) {
        float v0 = hidden[i];
        float v1 = hidden[BSZ * HDIM + i];
        g_h0f[i] = v0; g_h1f[i] = v1;
        __nv_bfloat16 h0 = __float2bfloat16(v0);
        __nv_bfloat16 h1 = __float2bfloat16(v1);
        g_h0_hi[i] = h0; g_h0_lo[i] = __float2bfloat16(v0 - __bfloat162float(h0));
        g_h1_hi[i] = h1; g_h1_lo[i] = __float2bfloat16(v1 - __bfloat162float(h1));
    }
    if (i < BSZ * DDIM) {
        g_out_hi[i] = __float2bfloat16(0.0f);
        g_out_lo[i] = __float2bfloat16(0.0f);
    }
}

// ============================ elementwise kernels ============================
__device__ __forceinline__ float sigmoidf_(float x) { return 1.0f / (1.0f + expf(-x)); }

__global__ void gru_gate(const float4* __restrict__ giA, const float4* __restrict__ giB,
                         const float4* __restrict__ ghA, const float4* __restrict__ ghB,
                         const float4* __restrict__ bih, const float4* __restrict__ bhh,
                         float4* __restrict__ h,
                         __nv_bfloat16* __restrict__ hhi, __nv_bfloat16* __restrict__ hlo)
{
    int idx = blockIdx.x * blockDim.x + threadIdx.x;   // B*H/4 threads
    int b = idx >> 8;
    int j = idx & 255;
    size_t o = (size_t)b * 768;
    float4 ir4, iz4, in4, hr4, hz4, hn4;
    {
        float4 a, c, bb;
        a = giA[o + j];       c = giB[o + j];       bb = bih[j];
        ir4 = make_float4(a.x+c.x+bb.x, a.y+c.y+bb.y, a.z+c.z+bb.z, a.w+c.w+bb.w);
        a = giA[o + 256 + j]; c = giB[o + 256 + j]; bb = bih[256 + j];
        iz4 = make_float4(a.x+c.x+bb.x, a.y+c.y+bb.y, a.z+c.z+bb.z, a.w+c.w+bb.w);
        a = giA[o + 512 + j]; c = giB[o + 512 + j]; bb = bih[512 + j];
        in4 = make_float4(a.x+c.x+bb.x, a.y+c.y+bb.y, a.z+c.z+bb.z, a.w+c.w+bb.w);
        a = ghA[o + j];       c = ghB[o + j];       bb = bhh[j];
        hr4 = make_float4(a.x+c.x+bb.x, a.y+c.y+bb.y, a.z+c.z+bb.z, a.w+c.w+bb.w);
        a = ghA[o + 256 + j]; c = ghB[o + 256 + j]; bb = bhh[256 + j];
        hz4 = make_float4(a.x+c.x+bb.x, a.y+c.y+bb.y, a.z+c.z+bb.z, a.w+c.w+bb.w);
        a = ghA[o + 512 + j]; c = ghB[o + 512 + j]; bb = bhh[512 + j];
        hn4 = make_float4(a.x+c.x+bb.x, a.y+c.y+bb.y, a.z+c.z+bb.z, a.w+c.w+bb.w);
    }
    float4 hv = h[idx];
    float irA[4] = {ir4.x, ir4.y, ir4.z, ir4.w}, izA[4] = {iz4.x, iz4.y, iz4.z, iz4.w};
    float inA[4] = {in4.x, in4.y, in4.z, in4.w};
    float hrA[4] = {hr4.x, hr4.y, hr4.z, hr4.w}, hzA[4] = {hz4.x, hz4.y, hz4.z, hz4.w};
    float hnA[4] = {hn4.x, hn4.y, hn4.z, hn4.w};
    float hvA[4] = {hv.x, hv.y, hv.z, hv.w};
    float out[4];
    #pragma unroll
    for (int k = 0; k < 4; k++) {
        float r = sigmoidf_(irA[k] + hrA[k]);
        float z = sigmoidf_(izA[k] + hzA[k]);
        float n = tanhf(inA[k] + r * hnA[k]);
        out[k] = (1.0f - z) * n + z * hvA[k];
    }
    h[idx] = make_float4(out[0], out[1], out[2], out[3]);
    int base = idx * 4;
    #pragma unroll
    for (int k = 0; k < 4; k++) {
        __nv_bfloat16 hb = __float2bfloat16(out[k]);
        hhi[base + k] = hb;
        hlo[base + k] = __float2bfloat16(out[k] - __bfloat162float(hb));
    }
}

template <int N>
__global__ void ln_gelu(const float* __restrict__ xa, const float* __restrict__ xb,
                        const float* __restrict__ fcb,
                        const float* __restrict__ g, const float* __restrict__ b,
                        __nv_bfloat16* __restrict__ hi, __nv_bfloat16* __restrict__ lo)
{
    const int row = blockIdx.x;
    const int tid = threadIdx.x;
    __shared__ float sv[N];

    float s = 0.0f, s2 = 0.0f;
    #pragma unroll
    for (int j = tid; j < N; j += 256) {
        float v = xa[(size_t)row * N + j] + xb[(size_t)row * N + j] + fcb[j];
        sv[j] = v;
        s += v; s2 += v * v;
    }
    __shared__ float rs[256], rs2[256];
    rs[tid] = s; rs2[tid] = s2;
    __syncthreads();
    #pragma unroll
    for (int o = 128; o > 0; o >>= 1) {
        if (tid < o) { rs[tid] += rs[tid + o]; rs2[tid] += rs2[tid + o]; }
        __syncthreads();
    }
    float mu  = rs[0]  * (1.0f / N);
    float var = rs2[0] * (1.0f / N) - mu * mu;
    float inv = rsqrtf(var + 1e-5f);

    #pragma unroll
    for (int j = tid; j < N; j += 256) {
        float v = (sv[j] - mu) * inv * g[j] + b[j];
        float gv = 0.5f * v * (1.0f + erff(v * 0.70710678118654752f));
        __nv_bfloat16 hb = __float2bfloat16(gv);
        hi[(size_t)row * N + j] = hb;
        lo[(size_t)row * N + j] = __float2bfloat16(gv - __bfloat162float(hb));
    }
}

__global__ void softmax_store(const float* __restrict__ za, const float* __restrict__ zb,
                              const float* __restrict__ fcb,
                              __nv_bfloat16* __restrict__ ohi, __nv_bfloat16* __restrict__ olo,
                              float* __restrict__ dst, int t)
{
    const int b = blockIdx.x;
    const int j = threadIdx.x;     // 256 == DDIM
    float v = za[(size_t)b * DDIM + j] + zb[(size_t)b * DDIM + j] + fcb[j];

    __shared__ float red[256];
    red[j] = v;
    __syncthreads();
    #pragma unroll
    for (int o = 128; o > 0; o >>= 1) {
        if (j < o) red[j] = fmaxf(red[j], red[j + o]);
        __syncthreads();
    }
    float m = red[0];
    __syncthreads();
    float e = expf(v - m);
    red[j] = e;
    __syncthreads();
    #pragma unroll
    for (int o = 128; o > 0; o >>= 1) {
        if (j < o) red[j] += red[j + o];
        __syncthreads();
    }
    float p = e / red[0];
    __nv_bfloat16 hb = __float2bfloat16(p);
    ohi[(size_t)b * DDIM + j] = hb;
    olo[(size_t)b * DDIM + j] = __float2bfloat16(p - __bfloat162float(hb));
    dst[((size_t)b * TLEN + t) * DDIM + j] = p;
}

// ===================== mma.sync split-bf16 batched GEMM ======================
// Per-job: C[M, N] = (Ahi+Alo)[M, kOff:kOff+kLen] @ (Bhi+Blo)[N, kOff:kOff+kLen]^T
// (lo*lo dropped).  No bias (consumers add).  blockIdx.z selects the job.
// 3-stage cp.async pipeline.
struct Job {
    const __nv_bfloat16 *Ahi, *Alo, *Bhi, *Blo;
    float* C;
    int K, kOff, kLen;
};
struct Jobs4 { Job j[4]; };

template <int BM, int BN, int WM, int WN>
__global__ __launch_bounds__(256)
void gemm_batch(Jobs4 jobs, int N)
{
    constexpr int PITCH = 80;
    constexpr int A_SZ  = BM * PITCH;
    constexpr int B_SZ  = BN * PITCH;
    constexpr int STAGE = 2 * A_SZ + 2 * B_SZ;
    constexpr int WARPS_N = BN / WN;
    constexpr int MT  = WM / 16;
    constexpr int NT  = WN / 8;
    constexpr int NT2 = WN / 16;

    extern __shared__ char smem[];
    const uint32_t sb = smem_u32(smem);
    const int tid  = threadIdx.x;
    const int wid  = tid >> 5;
    const int lane = tid & 31;
    const int wm0 = (wid / WARPS_N) * WM;
    const int wn0 = (wid % WARPS_N) * WN;
    const int row0 = blockIdx.y * BM;
    const int col0 = blockIdx.x * BN;

    const Job jb = jobs.j[blockIdx.z];
    const int K  = jb.K;
    const int NC = jb.kLen >> 5;
    const __nv_bfloat16* __restrict__ Ahi = jb.Ahi;
    const __nv_bfloat16* __restrict__ Alo = jb.Alo;
    const __nv_bfloat16* __restrict__ Bhi = jb.Bhi;
    const __nv_bfloat16* __restrict__ Blo = jb.Blo;

    float acc[MT][NT][4] = {};

    auto copy_chunk = [&](int c, int buf) {
        const uint32_t base = sb + buf * STAGE;
        const int kb = jb.kOff + (c << 5);
        #pragma unroll
        for (int i = tid; i < BM * 4; i += 256) {
            int r = i >> 2, q = i & 3;
            size_t g = (size_t)(row0 + r) * K + kb + q * 8;
            uint32_t d = base + r * PITCH + q * 16;
            cpasync16(d,        Ahi + g);
            cpasync16(d + A_SZ, Alo + g);
        }
        #pragma unroll
        for (int i = tid; i < BN * 4; i += 256) {
            int r = i >> 2, q = i & 3;
            size_t g = (size_t)(col0 + r) * K + kb + q * 8;
            uint32_t d = base + 2 * A_SZ + r * PITCH + q * 16;
            cpasync16(d,        Bhi + g);
            cpasync16(d + B_SZ, Blo + g);
        }
    };

    // 3-stage prologue
    copy_chunk(0, 0); CP_COMMIT;
    copy_chunk(1, 1); CP_COMMIT;

    for (int c = 0; c < NC; c++) {
        if (c < NC - 1) { CP_WAIT1; } else { CP_WAIT0; }
        __syncthreads();
        if (c + 2 < NC) { copy_chunk(c + 2, (c + 2) % 3); CP_COMMIT; }

        const uint32_t aBase = sb + (c % 3) * STAGE;
        const uint32_t bBase = aBase + 2 * A_SZ;

        #pragma unroll
        for (int ks = 0; ks < 2; ks++) {
            uint32_t ah[MT][4], al[MT][4], bh[NT2][4], bl[NT2][4];
            #pragma unroll
            for (int mt = 0; mt < MT; mt++) {
                uint32_t ad = aBase + (wm0 + mt * 16 + (lane & 15)) * PITCH
                            + ks * 32 + ((lane >> 4) << 4);
                ldmx4(ah[mt], ad);
                ldmx4(al[mt], ad + A_SZ);
            }
            #pragma unroll
            for (int n2 = 0; n2 < NT2; n2++) {
                int nr = wn0 + n2 * 16 + (lane & 7) + ((lane & 16) ? 8 : 0);
                uint32_t bd = bBase + nr * PITCH + ks * 32 + ((lane & 8) ? 16 : 0);
                ldmx4(bh[n2], bd);
                ldmx4(bl[n2], bd + B_SZ);
            }
            #pragma unroll
            for (int mt = 0; mt < MT; mt++)
                #pragma unroll
                for (int nt = 0; nt < NT; nt++) {
                    const uint32_t* bph = &bh[nt >> 1][(nt & 1) * 2];
                    const uint32_t* bpl = &bl[nt >> 1][(nt & 1) * 2];
                    mma_bf16(acc[mt][nt], ah[mt], bph);
                    mma_bf16(acc[mt][nt], ah[mt], bpl);
                    mma_bf16(acc[mt][nt], al[mt], bph);
                }
        }
        // top-of-loop __syncthreads covers buffer reuse (stage freed 3 iters ago)
    }

    float* __restrict__ C = jb.C;
    #pragma unroll
    for (int mt = 0; mt < MT; mt++) {
        int r0 = row0 + wm0 + mt * 16 + (lane >> 2);
        #pragma unroll
        for (int nt = 0; nt < NT; nt++) {
            int cc = col0 + wn0 + nt * 8 + (lane & 3) * 2;
            float2 v0 = { acc[mt][nt][0], acc[mt][nt][1] };
            float2 v1 = { acc[mt][nt][2], acc[mt][nt][3] };
            *(float2*)(C + (size_t)r0 * N + cc)       = v0;
            *(float2*)(C + (size_t)(r0 + 8) * N + cc) = v1;
        }
    }
}

// ============================ host side ======================================
#define SMEM_BIG   (3 * (2 * 128 * 80 + 2 * 64 * 80))   // 92160
#define SMEM_SMALL (3 * (2 * 64 * 80 + 2 * 64 * 80))    // 61440

extern "C" void kernel_launch(void* const* d_in, const int* in_sizes, int n_in,
                              void* d_out, int out_size)
{
    const float* hidden = (const float*)d_in[0];
    const float* W_ih0  = (const float*)d_in[1];
    const float* W_hh0  = (const float*)d_in[2];
    const float* b_ih0  = (const float*)d_in[3];
    const float* b_hh0  = (const float*)d_in[4];
    const float* W_ih1  = (const float*)d_in[5];
    const float* W_hh1  = (const float*)d_in[6];
    const float* b_ih1  = (const float*)d_in[7];
    const float* b_hh1  = (const float*)d_in[8];
    const float* fc1_w  = (const float*)d_in[9];
    const float* fc1_b  = (const float*)d_in[10];
    const float* ln1_g  = (const float*)d_in[11];
    const float* ln1_b  = (const float*)d_in[12];
    const float* fc2_w  = (const float*)d_in[13];
    const float* fc2_b  = (const float*)d_in[14];
    const float* ln2_g  = (const float*)d_in[15];
    const float* ln2_b  = (const float*)d_in[16];
    const float* fc3_w  = (const float*)d_in[17];
    const float* fc3_b  = (const float*)d_in[18];
    float* out = (float*)d_out;

    cudaFuncSetAttribute((const void*)gemm_batch<128, 64, 32, 32>,
                         cudaFuncAttributeMaxDynamicSharedMemorySize, SMEM_BIG);
    cudaFuncSetAttribute((const void*)gemm_batch<64, 64, 16, 32>,
                         cudaFuncAttributeMaxDynamicSharedMemorySize, SMEM_SMALL);

    float *giA, *giB, *ghA, *ghB, *z1A, *z1B, *z2A, *z2B, *z3A, *z3B, *h0f, *h1f;
    __nv_bfloat16 *ohi, *olo, *h0hi, *h0lo, *h1hi, *h1lo, *z1hi, *z1lo, *z2hi, *z2lo;
    __nv_bfloat16 *wih0h, *wih0l, *whh0h, *whh0l, *wih1h, *wih1l, *whh1h, *whh1l;
    __nv_bfloat16 *f1h, *f1l, *f2h, *f2l, *f3h, *f3l;
    cudaGetSymbolAddress((void**)&h0f, g_h0f);  cudaGetSymbolAddress((void**)&h1f, g_h1f);
    cudaGetSymbolAddress((void**)&giA, g_giA);  cudaGetSymbolAddress((void**)&giB, g_giB);
    cudaGetSymbolAddress((void**)&ghA, g_ghA);  cudaGetSymbolAddress((void**)&ghB, g_ghB);
    cudaGetSymbolAddress((void**)&z1A, g_z1A);  cudaGetSymbolAddress((void**)&z1B, g_z1B);
    cudaGetSymbolAddress((void**)&z2A, g_z2A);  cudaGetSymbolAddress((void**)&z2B, g_z2B);
    cudaGetSymbolAddress((void**)&z3A, g_z3A);  cudaGetSymbolAddress((void**)&z3B, g_z3B);
    cudaGetSymbolAddress((void**)&ohi, g_out_hi); cudaGetSymbolAddress((void**)&olo, g_out_lo);
    cudaGetSymbolAddress((void**)&h0hi, g_h0_hi); cudaGetSymbolAddress((void**)&h0lo, g_h0_lo);
    cudaGetSymbolAddress((void**)&h1hi, g_h1_hi); cudaGetSymbolAddress((void**)&h1lo, g_h1_lo);
    cudaGetSymbolAddress((void**)&z1hi, g_z1_hi); cudaGetSymbolAddress((void**)&z1lo, g_z1_lo);
    cudaGetSymbolAddress((void**)&z2hi, g_z2_hi); cudaGetSymbolAddress((void**)&z2lo, g_z2_lo);
    cudaGetSymbolAddress((void**)&wih0h, g_wih0_hi); cudaGetSymbolAddress((void**)&wih0l, g_wih0_lo);
    cudaGetSymbolAddress((void**)&whh0h, g_whh0_hi); cudaGetSymbolAddress((void**)&whh0l, g_whh0_lo);
    cudaGetSymbolAddress((void**)&wih1h, g_wih1_hi); cudaGetSymbolAddress((void**)&wih1l, g_wih1_lo);
    cudaGetSymbolAddress((void**)&whh1h, g_whh1_hi); cudaGetSymbolAddress((void**)&whh1l, g_whh1_lo);
    cudaGetSymbolAddress((void**)&f1h, g_fc1_hi); cudaGetSymbolAddress((void**)&f1l, g_fc1_lo);
    cudaGetSymbolAddress((void**)&f2h, g_fc2_hi); cudaGetSymbolAddress((void**)&f2l, g_fc2_lo);
    cudaGetSymbolAddress((void**)&f3h, g_fc3_hi); cudaGetSymbolAddress((void**)&f3l, g_fc3_lo);

    // setup = exactly 3 launches, so ncu (-s 5 -c 1) captures the 6th launch:
    // [1] splitA  [2] splitB  [3] init  [4] L0-gemm  [5] gate0  [6] L1-gemm <- profiled
    {
        SplitJobs JA;
        JA.j[0] = { W_ih0, wih0h, wih0l, 3 * HDIM * DDIM };
        JA.j[1] = { W_hh0, whh0h, whh0l, 3 * HDIM * HDIM };
        JA.j[2] = { W_ih1, wih1h, wih1l, 3 * HDIM * HDIM };
        JA.cnt = 3;
        split_multi<<<2048, 256>>>(JA);
        SplitJobs JB;
        JB.j[0] = { W_hh1, whh1h, whh1l, 3 * HDIM * HDIM };
        JB.j[1] = { fc1_w, f1h, f1l, FC1N * HDIM };
        JB.j[2] = { fc2_w, f2h, f2l, FC2N * FC1N };
        JB.j[3] = { fc3_w, f3h, f3l, DDIM * FC2N };
        JB.cnt = 4;
        split_multi<<<2048, 256>>>(JB);
    }
    init_kernel<<<(BSZ * HDIM + 255) / 256, 256>>>(hidden);

    for (int t = 0; t < TLEN; t++) {
        // ---- GRU layer 0: 4 sub-jobs in one launch (384 CTAs) ----
        {
            Jobs4 J;
            J.j[0] = { ohi,  olo,  wih0h, wih0l, giA, DDIM, 0,   128 };
            J.j[1] = { ohi,  olo,  wih0h, wih0l, giB, DDIM, 128, 128 };
            J.j[2] = { h0hi, h0lo, whh0h, whh0l, ghA, HDIM, 0,   512 };
            J.j[3] = { h0hi, h0lo, whh0h, whh0l, ghB, HDIM, 512, 512 };
            dim3 grid(3 * HDIM / 64, BSZ / 128, 4);
            gemm_batch<128, 64, 32, 32><<<grid, 256, SMEM_BIG>>>(J, 3 * HDIM);
        }
        gru_gate<<<(BSZ * HDIM / 4) / 256, 256>>>(
            (const float4*)giA, (const float4*)giB, (const float4*)ghA, (const float4*)ghB,
            (const float4*)b_ih0, (const float4*)b_hh0, (float4*)h0f, h0hi, h0lo);

        // ---- GRU layer 1: 4 sub-jobs in one launch (384 CTAs) ----
        {
            Jobs4 J;
            J.j[0] = { h0hi, h0lo, wih1h, wih1l, giA, HDIM, 0,   512 };
            J.j[1] = { h0hi, h0lo, wih1h, wih1l, giB, HDIM, 512, 512 };
            J.j[2] = { h1hi, h1lo, whh1h, whh1l, ghA, HDIM, 0,   512 };
            J.j[3] = { h1hi, h1lo, whh1h, whh1l, ghB, HDIM, 512, 512 };
            dim3 grid(3 * HDIM / 64, BSZ / 128, 4);
            gemm_batch<128, 64, 32, 32><<<grid, 256, SMEM_BIG>>>(J, 3 * HDIM);
        }
        gru_gate<<<(BSZ * HDIM / 4) / 256, 256>>>(
            (const float4*)giA, (const float4*)giB, (const float4*)ghA, (const float4*)ghB,
            (const float4*)b_ih1, (const float4*)b_hh1, (float4*)h1f, h1hi, h1lo);

        // ---- FC head (split-K=2, BM=64 tiles) ----
        {
            Jobs4 J;
            J.j[0] = { h1hi, h1lo, f1h, f1l, z1A, HDIM, 0,   512 };
            J.j[1] = { h1hi, h1lo, f1h, f1l, z1B, HDIM, 512, 512 };
            dim3 grid(FC1N / 64, BSZ / 64, 2);
            gemm_batch<64, 64, 16, 32><<<grid, 256, SMEM_SMALL>>>(J, FC1N);
        }
        ln_gelu<FC1N><<<BSZ, 256>>>(z1A, z1B, fc1_b, ln1_g, ln1_b, z1hi, z1lo);
        {
            Jobs4 J;
            J.j[0] = { z1hi, z1lo, f2h, f2l, z2A, FC1N, 0,   512 };
            J.j[1] = { z1hi, z1lo, f2h, f2l, z2B, FC1N, 512, 512 };
            dim3 grid(FC2N / 64, BSZ / 64, 2);
            gemm_batch<64, 64, 16, 32><<<grid, 256, SMEM_SMALL>>>(J, FC2N);
        }
        ln_gelu<FC2N><<<BSZ, 256>>>(z2A, z2B, fc2_b, ln2_g, ln2_b, z2hi, z2lo);
        {
            Jobs4 J;
            J.j[0] = { z2hi, z2lo, f3h, f3l, z3A, FC2N, 0,   256 };
            J.j[1] = { z2hi, z2lo, f3h, f3l, z3B, FC2N, 256, 256 };
            dim3 grid(DDIM / 64, BSZ / 64, 2);
            gemm_batch<64, 64, 16, 32><<<grid, 256, SMEM_SMALL>>>(J, DDIM);
        }
        softmax_store<<<BSZ, DDIM>>>(z3A, z3B, fc3_b, ohi, olo, out, t);
    }
}

// round 13
// speedup vs baseline: 1.0474x; 1.0311x over previous
#include <cuda_runtime.h>
#include <cuda_bf16.h>
#include <math.h>
#include <stdint.h>

#define BSZ  256
#define HDIM 1024
#define DDIM 256
#define TLEN 64
#define FC1N 1024
#define FC2N 512

// ============================ PTX helpers ====================================
__device__ __forceinline__ uint32_t smem_u32(const void* p) {
    uint32_t a;
    asm("{ .reg .u64 t; cvta.to.shared.u64 t, %1; cvt.u32.u64 %0, t; }" : "=r"(a) : "l"(p));
    return a;
}
__device__ __forceinline__ void ldmx4(uint32_t* r, uint32_t addr) {
    asm volatile("ldmatrix.sync.aligned.m8n8.x4.shared.b16 {%0,%1,%2,%3}, [%4];"
        : "=r"(r[0]), "=r"(r[1]), "=r"(r[2]), "=r"(r[3]) : "r"(addr));
}
__device__ __forceinline__ void mma_bf16(float* d, const uint32_t* a, const uint32_t* b) {
    asm volatile("mma.sync.aligned.m16n8k16.row.col.f32.bf16.bf16.f32 "
        "{%0,%1,%2,%3}, {%4,%5,%6,%7}, {%8,%9}, {%0,%1,%2,%3};"
        : "+f"(d[0]), "+f"(d[1]), "+f"(d[2]), "+f"(d[3])
        : "r"(a[0]), "r"(a[1]), "r"(a[2]), "r"(a[3]), "r"(b[0]), "r"(b[1]));
}
__device__ __forceinline__ void cpasync16(uint32_t dst, const void* src) {
    asm volatile("cp.async.cg.shared.global [%0], [%1], 16;" :: "r"(dst), "l"(src));
}
#define CP_COMMIT asm volatile("cp.async.commit_group;" ::: "memory")
#define CP_WAIT0  asm volatile("cp.async.wait_group 0;" ::: "memory")

// ====================== persistent device scratch ============================
__device__ float g_h0f[BSZ * HDIM];
__device__ float g_h1f[BSZ * HDIM];
__device__ float g_giA[BSZ * 3 * HDIM], g_giB[BSZ * 3 * HDIM];
__device__ float g_ghA[BSZ * 3 * HDIM], g_ghB[BSZ * 3 * HDIM];
__device__ float g_z1A[BSZ * FC1N], g_z1B[BSZ * FC1N];
__device__ float g_z2A[BSZ * FC2N], g_z2B[BSZ * FC2N];
__device__ float g_z3A[BSZ * DDIM], g_z3B[BSZ * DDIM];
__device__ __nv_bfloat16 g_out_hi[BSZ * DDIM],  g_out_lo[BSZ * DDIM];
__device__ __nv_bfloat16 g_h0_hi [BSZ * HDIM],  g_h0_lo [BSZ * HDIM];
__device__ __nv_bfloat16 g_h1_hi [BSZ * HDIM],  g_h1_lo [BSZ * HDIM];
__device__ __nv_bfloat16 g_z1_hi [BSZ * FC1N],  g_z1_lo [BSZ * FC1N];
__device__ __nv_bfloat16 g_z2_hi [BSZ * FC2N],  g_z2_lo [BSZ * FC2N];
__device__ __nv_bfloat16 g_wih0_hi[3*HDIM*DDIM], g_wih0_lo[3*HDIM*DDIM];
__device__ __nv_bfloat16 g_whh0_hi[3*HDIM*HDIM], g_whh0_lo[3*HDIM*HDIM];
__device__ __nv_bfloat16 g_wih1_hi[3*HDIM*HDIM], g_wih1_lo[3*HDIM*HDIM];
__device__ __nv_bfloat16 g_whh1_hi[3*HDIM*HDIM], g_whh1_lo[3*HDIM*HDIM];
__device__ __nv_bfloat16 g_fc1_hi[FC1N*HDIM],    g_fc1_lo[FC1N*HDIM];
__device__ __nv_bfloat16 g_fc2_hi[FC2N*FC1N],    g_fc2_lo[FC2N*FC1N];
__device__ __nv_bfloat16 g_fc3_hi[DDIM*FC2N],    g_fc3_lo[DDIM*FC2N];

// ============================ setup kernels ==================================
struct SplitJob { const float* src; __nv_bfloat16* hi; __nv_bfloat16* lo; int n; };
struct SplitJobs { SplitJob j[4]; int cnt; };

__global__ void split_multi(SplitJobs J) {
    for (int jb = 0; jb < J.cnt; jb++) {
        const float* __restrict__ src = J.j[jb].src;
        __nv_bfloat16* __restrict__ hi = J.j[jb].hi;
        __nv_bfloat16* __restrict__ lo = J.j[jb].lo;
        const int n = J.j[jb].n;
        for (int i = blockIdx.x * blockDim.x + threadIdx.x; i < n;
             i += gridDim.x * blockDim.x) {
            float v = src[i];
            __nv_bfloat16 h = __float2bfloat16(v);
            hi[i] = h;
            lo[i] = __float2bfloat16(v - __bfloat162float(h));
        }
    }
}

__global__ void init_kernel(const float* __restrict__ hidden) {
    int i = blockIdx.x * blockDim.x + threadIdx.x;
    if (i < BSZ * HDIM) {
        float v0 = hidden[i];
        float v1 = hidden[BSZ * HDIM + i];
        g_h0f[i] = v0; g_h1f[i] = v1;
        __nv_bfloat16 h0 = __float2bfloat16(v0);
        __nv_bfloat16 h1 = __float2bfloat16(v1);
        g_h0_hi[i] = h0; g_h0_lo[i] = __float2bfloat16(v0 - __bfloat162float(h0));
        g_h1_hi[i] = h1; g_h1_lo[i] = __float2bfloat16(v1 - __bfloat162float(h1));
    }
    if (i < BSZ * DDIM) {
        g_out_hi[i] = __float2bfloat16(0.0f);
        g_out_lo[i] = __float2bfloat16(0.0f);
    }
}

// ============================ elementwise kernels ============================
__device__ __forceinline__ float sigmoidf_(float x) { return 1.0f / (1.0f + expf(-x)); }

__global__ void gru_gate(const float4* __restrict__ giA, const float4* __restrict__ giB,
                         const float4* __restrict__ ghA, const float4* __restrict__ ghB,
                         const float4* __restrict__ bih, const float4* __restrict__ bhh,
                         float4* __restrict__ h,
                         __nv_bfloat16* __restrict__ hhi, __nv_bfloat16* __restrict__ hlo)
{
    int idx = blockIdx.x * blockDim.x + threadIdx.x;   // B*H/4 threads
    int b = idx >> 8;
    int j = idx & 255;
    size_t o = (size_t)b * 768;
    float4 ir4, iz4, in4, hr4, hz4, hn4;
    {
        float4 a, c, bb;
        a = giA[o + j];       c = giB[o + j];       bb = bih[j];
        ir4 = make_float4(a.x+c.x+bb.x, a.y+c.y+bb.y, a.z+c.z+bb.z, a.w+c.w+bb.w);
        a = giA[o + 256 + j]; c = giB[o + 256 + j]; bb = bih[256 + j];
        iz4 = make_float4(a.x+c.x+bb.x, a.y+c.y+bb.y, a.z+c.z+bb.z, a.w+c.w+bb.w);
        a = giA[o + 512 + j]; c = giB[o + 512 + j]; bb = bih[512 + j];
        in4 = make_float4(a.x+c.x+bb.x, a.y+c.y+bb.y, a.z+c.z+bb.z, a.w+c.w+bb.w);
        a = ghA[o + j];       c = ghB[o + j];       bb = bhh[j];
        hr4 = make_float4(a.x+c.x+bb.x, a.y+c.y+bb.y, a.z+c.z+bb.z, a.w+c.w+bb.w);
        a = ghA[o + 256 + j]; c = ghB[o + 256 + j]; bb = bhh[256 + j];
        hz4 = make_float4(a.x+c.x+bb.x, a.y+c.y+bb.y, a.z+c.z+bb.z, a.w+c.w+bb.w);
        a = ghA[o + 512 + j]; c = ghB[o + 512 + j]; bb = bhh[512 + j];
        hn4 = make_float4(a.x+c.x+bb.x, a.y+c.y+bb.y, a.z+c.z+bb.z, a.w+c.w+bb.w);
    }
    float4 hv = h[idx];
    float irA[4] = {ir4.x, ir4.y, ir4.z, ir4.w}, izA[4] = {iz4.x, iz4.y, iz4.z, iz4.w};
    float inA[4] = {in4.x, in4.y, in4.z, in4.w};
    float hrA[4] = {hr4.x, hr4.y, hr4.z, hr4.w}, hzA[4] = {hz4.x, hz4.y, hz4.z, hz4.w};
    float hnA[4] = {hn4.x, hn4.y, hn4.z, hn4.w};
    float hvA[4] = {hv.x, hv.y, hv.z, hv.w};
    float out[4];
    #pragma unroll
    for (int k = 0; k < 4; k++) {
        float r = sigmoidf_(irA[k] + hrA[k]);
        float z = sigmoidf_(izA[k] + hzA[k]);
        float n = tanhf(inA[k] + r * hnA[k]);
        out[k] = (1.0f - z) * n + z * hvA[k];
    }
    h[idx] = make_float4(out[0], out[1], out[2], out[3]);
    int base = idx * 4;
    #pragma unroll
    for (int k = 0; k < 4; k++) {
        __nv_bfloat16 hb = __float2bfloat16(out[k]);
        hhi[base + k] = hb;
        hlo[base + k] = __float2bfloat16(out[k] - __bfloat162float(hb));
    }
}

template <int N>
__global__ void ln_gelu(const float* __restrict__ xa, const float* __restrict__ xb,
                        const float* __restrict__ fcb,
                        const float* __restrict__ g, const float* __restrict__ b,
                        __nv_bfloat16* __restrict__ hi, __nv_bfloat16* __restrict__ lo)
{
    const int row = blockIdx.x;
    const int tid = threadIdx.x;
    __shared__ float sv[N];

    float s = 0.0f, s2 = 0.0f;
    #pragma unroll
    for (int j = tid; j < N; j += 256) {
        float v = xa[(size_t)row * N + j] + xb[(size_t)row * N + j] + fcb[j];
        sv[j] = v;
        s += v; s2 += v * v;
    }
    __shared__ float rs[256], rs2[256];
    rs[tid] = s; rs2[tid] = s2;
    __syncthreads();
    #pragma unroll
    for (int o = 128; o > 0; o >>= 1) {
        if (tid < o) { rs[tid] += rs[tid + o]; rs2[tid] += rs2[tid + o]; }
        __syncthreads();
    }
    float mu  = rs[0]  * (1.0f / N);
    float var = rs2[0] * (1.0f / N) - mu * mu;
    float inv = rsqrtf(var + 1e-5f);

    #pragma unroll
    for (int j = tid; j < N; j += 256) {
        float v = (sv[j] - mu) * inv * g[j] + b[j];
        float gv = 0.5f * v * (1.0f + erff(v * 0.70710678118654752f));
        __nv_bfloat16 hb = __float2bfloat16(gv);
        hi[(size_t)row * N + j] = hb;
        lo[(size_t)row * N + j] = __float2bfloat16(gv - __bfloat162float(hb));
    }
}

__global__ void softmax_store(const float* __restrict__ za, const float* __restrict__ zb,
                              const float* __restrict__ fcb,
                              __nv_bfloat16* __restrict__ ohi, __nv_bfloat16* __restrict__ olo,
                              float* __restrict__ dst, int t)
{
    const int b = blockIdx.x;
    const int j = threadIdx.x;     // 256 == DDIM
    float v = za[(size_t)b * DDIM + j] + zb[(size_t)b * DDIM + j] + fcb[j];

    __shared__ float red[256];
    red[j] = v;
    __syncthreads();
    #pragma unroll
    for (int o = 128; o > 0; o >>= 1) {
        if (j < o) red[j] = fmaxf(red[j], red[j + o]);
        __syncthreads();
    }
    float m = red[0];
    __syncthreads();
    float e = expf(v - m);
    red[j] = e;
    __syncthreads();
    #pragma unroll
    for (int o = 128; o > 0; o >>= 1) {
        if (j < o) red[j] += red[j + o];
        __syncthreads();
    }
    float p = e / red[0];
    __nv_bfloat16 hb = __float2bfloat16(p);
    ohi[(size_t)b * DDIM + j] = hb;
    olo[(size_t)b * DDIM + j] = __float2bfloat16(p - __bfloat162float(hb));
    dst[((size_t)b * TLEN + t) * DDIM + j] = p;
}

// ===================== mma.sync split-bf16 batched GEMM ======================
// Per-job: C[M, N] = (Ahi+Alo)[M, kOff:kOff+kLen] @ (Bhi+Blo)[N, kOff:kOff+kLen]^T
// (lo*lo dropped).  No bias (consumers add).  blockIdx.z selects the job.
// 2-stage cp.async pipeline.  THREADS derived from warp tiling.
struct Job {
    const __nv_bfloat16 *Ahi, *Alo, *Bhi, *Blo;
    float* C;
    int K, kOff, kLen;
};
struct Jobs4 { Job j[4]; };

template <int BM, int BN, int WM, int WN>
__global__ __launch_bounds__((BM/WM)*(BN/WN)*32, 384/((BM/WM)*(BN/WN)*32))
void gemm_batch(Jobs4 jobs, int N)
{
    constexpr int THREADS = (BM/WM)*(BN/WN)*32;
    constexpr int PITCH = 80;
    constexpr int A_SZ  = BM * PITCH;
    constexpr int B_SZ  = BN * PITCH;
    constexpr int STAGE = 2 * A_SZ + 2 * B_SZ;
    constexpr int WARPS_N = BN / WN;
    constexpr int MT  = WM / 16;
    constexpr int NT  = WN / 8;
    constexpr int NT2 = WN / 16;

    extern __shared__ char smem[];
    const uint32_t sb = smem_u32(smem);
    const int tid  = threadIdx.x;
    const int wid  = tid >> 5;
    const int lane = tid & 31;
    const int wm0 = (wid / WARPS_N) * WM;
    const int wn0 = (wid % WARPS_N) * WN;
    const int row0 = blockIdx.y * BM;
    const int col0 = blockIdx.x * BN;

    const Job jb = jobs.j[blockIdx.z];
    const int K  = jb.K;
    const int NC = jb.kLen >> 5;
    const __nv_bfloat16* __restrict__ Ahi = jb.Ahi;
    const __nv_bfloat16* __restrict__ Alo = jb.Alo;
    const __nv_bfloat16* __restrict__ Bhi = jb.Bhi;
    const __nv_bfloat16* __restrict__ Blo = jb.Blo;

    float acc[MT][NT][4] = {};

    auto copy_chunk = [&](int c, int buf) {
        const uint32_t base = sb + buf * STAGE;
        const int kb = jb.kOff + (c << 5);
        #pragma unroll
        for (int i = tid; i < BM * 4; i += THREADS) {
            int r = i >> 2, q = i & 3;
            size_t g = (size_t)(row0 + r) * K + kb + q * 8;
            uint32_t d = base + r * PITCH + q * 16;
            cpasync16(d,        Ahi + g);
            cpasync16(d + A_SZ, Alo + g);
        }
        #pragma unroll
        for (int i = tid; i < BN * 4; i += THREADS) {
            int r = i >> 2, q = i & 3;
            size_t g = (size_t)(col0 + r) * K + kb + q * 8;
            uint32_t d = base + 2 * A_SZ + r * PITCH + q * 16;
            cpasync16(d,        Bhi + g);
            cpasync16(d + B_SZ, Blo + g);
        }
    };

    copy_chunk(0, 0);
    CP_COMMIT;

    for (int c = 0; c < NC; c++) {
        CP_WAIT0;
        __syncthreads();
        if (c + 1 < NC) { copy_chunk(c + 1, (c + 1) & 1); CP_COMMIT; }

        const uint32_t aBase = sb + (c & 1) * STAGE;
        const uint32_t bBase = aBase + 2 * A_SZ;

        #pragma unroll
        for (int ks = 0; ks < 2; ks++) {
            uint32_t ah[MT][4], al[MT][4];
            #pragma unroll
            for (int mt = 0; mt < MT; mt++) {
                uint32_t ad = aBase + (wm0 + mt * 16 + (lane & 15)) * PITCH
                            + ks * 32 + ((lane >> 4) << 4);
                ldmx4(ah[mt], ad);
                ldmx4(al[mt], ad + A_SZ);
            }
            #pragma unroll
            for (int n2 = 0; n2 < NT2; n2++) {
                uint32_t bh[4], bl[4];
                int nr = wn0 + n2 * 16 + (lane & 7) + ((lane & 16) ? 8 : 0);
                uint32_t bd = bBase + nr * PITCH + ks * 32 + ((lane & 8) ? 16 : 0);
                ldmx4(bh, bd);
                ldmx4(bl, bd + B_SZ);
                #pragma unroll
                for (int mt = 0; mt < MT; mt++)
                    #pragma unroll
                    for (int half = 0; half < 2; half++) {
                        int nt = n2 * 2 + half;
                        mma_bf16(acc[mt][nt], ah[mt], &bh[half * 2]);
                        mma_bf16(acc[mt][nt], ah[mt], &bl[half * 2]);
                        mma_bf16(acc[mt][nt], al[mt], &bh[half * 2]);
                    }
            }
        }
        __syncthreads();
    }

    float* __restrict__ C = jb.C;
    #pragma unroll
    for (int mt = 0; mt < MT; mt++) {
        int r0 = row0 + wm0 + mt * 16 + (lane >> 2);
        #pragma unroll
        for (int nt = 0; nt < NT; nt++) {
            int cc = col0 + wn0 + nt * 8 + (lane & 3) * 2;
            float2 v0 = { acc[mt][nt][0], acc[mt][nt][1] };
            float2 v1 = { acc[mt][nt][2], acc[mt][nt][3] };
            *(float2*)(C + (size_t)r0 * N + cc)       = v0;
            *(float2*)(C + (size_t)(r0 + 8) * N + cc) = v1;
        }
    }
}

// ============================ host side ======================================
// big:   128x64 CTA tile, 4 warps (128 thr), warp tile 32x64, 2-stage
// small: 64x64 CTA tile, 8 warps (256 thr), warp tile 16x32, 2-stage
#define SMEM_BIG   (2 * (2 * 128 * 80 + 2 * 64 * 80))   // 61440 -> 3 CTAs/SM
#define SMEM_SMALL (2 * (2 * 64 * 80 + 2 * 64 * 80))    // 40960

extern "C" void kernel_launch(void* const* d_in, const int* in_sizes, int n_in,
                              void* d_out, int out_size)
{
    const float* hidden = (const float*)d_in[0];
    const float* W_ih0  = (const float*)d_in[1];
    const float* W_hh0  = (const float*)d_in[2];
    const float* b_ih0  = (const float*)d_in[3];
    const float* b_hh0  = (const float*)d_in[4];
    const float* W_ih1  = (const float*)d_in[5];
    const float* W_hh1  = (const float*)d_in[6];
    const float* b_ih1  = (const float*)d_in[7];
    const float* b_hh1  = (const float*)d_in[8];
    const float* fc1_w  = (const float*)d_in[9];
    const float* fc1_b  = (const float*)d_in[10];
    const float* ln1_g  = (const float*)d_in[11];
    const float* ln1_b  = (const float*)d_in[12];
    const float* fc2_w  = (const float*)d_in[13];
    const float* fc2_b  = (const float*)d_in[14];
    const float* ln2_g  = (const float*)d_in[15];
    const float* ln2_b  = (const float*)d_in[16];
    const float* fc3_w  = (const float*)d_in[17];
    const float* fc3_b  = (const float*)d_in[18];
    float* out = (float*)d_out;

    cudaFuncSetAttribute((const void*)gemm_batch<128, 64, 32, 64>,
                         cudaFuncAttributeMaxDynamicSharedMemorySize, SMEM_BIG);
    cudaFuncSetAttribute((const void*)gemm_batch<64, 64, 16, 32>,
                         cudaFuncAttributeMaxDynamicSharedMemorySize, SMEM_SMALL);

    float *giA, *giB, *ghA, *ghB, *z1A, *z1B, *z2A, *z2B, *z3A, *z3B, *h0f, *h1f;
    __nv_bfloat16 *ohi, *olo, *h0hi, *h0lo, *h1hi, *h1lo, *z1hi, *z1lo, *z2hi, *z2lo;
    __nv_bfloat16 *wih0h, *wih0l, *whh0h, *whh0l, *wih1h, *wih1l, *whh1h, *whh1l;
    __nv_bfloat16 *f1h, *f1l, *f2h, *f2l, *f3h, *f3l;
    cudaGetSymbolAddress((void**)&h0f, g_h0f);  cudaGetSymbolAddress((void**)&h1f, g_h1f);
    cudaGetSymbolAddress((void**)&giA, g_giA);  cudaGetSymbolAddress((void**)&giB, g_giB);
    cudaGetSymbolAddress((void**)&ghA, g_ghA);  cudaGetSymbolAddress((void**)&ghB, g_ghB);
    cudaGetSymbolAddress((void**)&z1A, g_z1A);  cudaGetSymbolAddress((void**)&z1B, g_z1B);
    cudaGetSymbolAddress((void**)&z2A, g_z2A);  cudaGetSymbolAddress((void**)&z2B, g_z2B);
    cudaGetSymbolAddress((void**)&z3A, g_z3A);  cudaGetSymbolAddress((void**)&z3B, g_z3B);
    cudaGetSymbolAddress((void**)&ohi, g_out_hi); cudaGetSymbolAddress((void**)&olo, g_out_lo);
    cudaGetSymbolAddress((void**)&h0hi, g_h0_hi); cudaGetSymbolAddress((void**)&h0lo, g_h0_lo);
    cudaGetSymbolAddress((void**)&h1hi, g_h1_hi); cudaGetSymbolAddress((void**)&h1lo, g_h1_lo);
    cudaGetSymbolAddress((void**)&z1hi, g_z1_hi); cudaGetSymbolAddress((void**)&z1lo, g_z1_lo);
    cudaGetSymbolAddress((void**)&z2hi, g_z2_hi); cudaGetSymbolAddress((void**)&z2lo, g_z2_lo);
    cudaGetSymbolAddress((void**)&wih0h, g_wih0_hi); cudaGetSymbolAddress((void**)&wih0l, g_wih0_lo);
    cudaGetSymbolAddress((void**)&whh0h, g_whh0_hi); cudaGetSymbolAddress((void**)&whh0l, g_whh0_lo);
    cudaGetSymbolAddress((void**)&wih1h, g_wih1_hi); cudaGetSymbolAddress((void**)&wih1l, g_wih1_lo);
    cudaGetSymbolAddress((void**)&whh1h, g_whh1_hi); cudaGetSymbolAddress((void**)&whh1l, g_whh1_lo);
    cudaGetSymbolAddress((void**)&f1h, g_fc1_hi); cudaGetSymbolAddress((void**)&f1l, g_fc1_lo);
    cudaGetSymbolAddress((void**)&f2h, g_fc2_hi); cudaGetSymbolAddress((void**)&f2l, g_fc2_lo);
    cudaGetSymbolAddress((void**)&f3h, g_fc3_hi); cudaGetSymbolAddress((void**)&f3l, g_fc3_lo);

    // setup = exactly 3 launches, so ncu (-s 5 -c 1) captures the 6th launch:
    // [1] splitA  [2] splitB  [3] init  [4] L0-gemm  [5] gate0  [6] L1-gemm <- profiled
    {
        SplitJobs JA;
        JA.j[0] = { W_ih0, wih0h, wih0l, 3 * HDIM * DDIM };
        JA.j[1] = { W_hh0, whh0h, whh0l, 3 * HDIM * HDIM };
        JA.j[2] = { W_ih1, wih1h, wih1l, 3 * HDIM * HDIM };
        JA.cnt = 3;
        split_multi<<<2048, 256>>>(JA);
        SplitJobs JB;
        JB.j[0] = { W_hh1, whh1h, whh1l, 3 * HDIM * HDIM };
        JB.j[1] = { fc1_w, f1h, f1l, FC1N * HDIM };
        JB.j[2] = { fc2_w, f2h, f2l, FC2N * FC1N };
        JB.j[3] = { fc3_w, f3h, f3l, DDIM * FC2N };
        JB.cnt = 4;
        split_multi<<<2048, 256>>>(JB);
    }
    init_kernel<<<(BSZ * HDIM + 255) / 256, 256>>>(hidden);

    for (int t = 0; t < TLEN; t++) {
        // ---- GRU layer 0: 4 sub-jobs in one launch (384 CTAs, 1 wave @3/SM) ----
        {
            Jobs4 J;
            J.j[0] = { ohi,  olo,  wih0h, wih0l, giA, DDIM, 0,   128 };
            J.j[1] = { ohi,  olo,  wih0h, wih0l, giB, DDIM, 128, 128 };
            J.j[2] = { h0hi, h0lo, whh0h, whh0l, ghA, HDIM, 0,   512 };
            J.j[3] = { h0hi, h0lo, whh0h, whh0l, ghB, HDIM, 512, 512 };
            dim3 grid(3 * HDIM / 64, BSZ / 128, 4);
            gemm_batch<128, 64, 32, 64><<<grid, 128, SMEM_BIG>>>(J, 3 * HDIM);
        }
        gru_gate<<<(BSZ * HDIM / 4) / 256, 256>>>(
            (const float4*)giA, (const float4*)giB, (const float4*)ghA, (const float4*)ghB,
            (const float4*)b_ih0, (const float4*)b_hh0, (float4*)h0f, h0hi, h0lo);

        // ---- GRU layer 1: 4 sub-jobs in one launch (384 CTAs, 1 wave @3/SM) ----
        {
            Jobs4 J;
            J.j[0] = { h0hi, h0lo, wih1h, wih1l, giA, HDIM, 0,   512 };
            J.j[1] = { h0hi, h0lo, wih1h, wih1l, giB, HDIM, 512, 512 };
            J.j[2] = { h1hi, h1lo, whh1h, whh1l, ghA, HDIM, 0,   512 };
            J.j[3] = { h1hi, h1lo, whh1h, whh1l, ghB, HDIM, 512, 512 };
            dim3 grid(3 * HDIM / 64, BSZ / 128, 4);
            gemm_batch<128, 64, 32, 64><<<grid, 128, SMEM_BIG>>>(J, 3 * HDIM);
        }
        gru_gate<<<(BSZ * HDIM / 4) / 256, 256>>>(
            (const float4*)giA, (const float4*)giB, (const float4*)ghA, (const float4*)ghB,
            (const float4*)b_ih1, (const float4*)b_hh1, (float4*)h1f, h1hi, h1lo);

        // ---- FC head (split-K=2, BM=64 tiles) ----
        {
            Jobs4 J;
            J.j[0] = { h1hi, h1lo, f1h, f1l, z1A, HDIM, 0,   512 };
            J.j[1] = { h1hi, h1lo, f1h, f1l, z1B, HDIM, 512, 512 };
            dim3 grid(FC1N / 64, BSZ / 64, 2);
            gemm_batch<64, 64, 16, 32><<<grid, 256, SMEM_SMALL>>>(J, FC1N);
        }
        ln_gelu<FC1N><<<BSZ, 256>>>(z1A, z1B, fc1_b, ln1_g, ln1_b, z1hi, z1lo);
        {
            Jobs4 J;
            J.j[0] = { z1hi, z1lo, f2h, f2l, z2A, FC1N, 0,   512 };
            J.j[1] = { z1hi, z1lo, f2h, f2l, z2B, FC1N, 512, 512 };
            dim3 grid(FC2N / 64, BSZ / 64, 2);
            gemm_batch<64, 64, 16, 32><<<grid, 256, SMEM_SMALL>>>(J, FC2N);
        }
        ln_gelu<FC2N><<<BSZ, 256>>>(z2A, z2B, fc2_b, ln2_g, ln2_b, z2hi, z2lo);
        {
            Jobs4 J;
            J.j[0] = { z2hi, z2lo, f3h, f3l, z3A, FC2N, 0,   256 };
            J.j[1] = { z2hi, z2lo, f3h, f3l, z3B, FC2N, 256, 256 };
            dim3 grid(DDIM / 64, BSZ / 64, 2);
            gemm_batch<64, 64, 16, 32><<<grid, 256, SMEM_SMALL>>>(J, DDIM);
        }
        softmax_store<<<BSZ, DDIM>>>(z3A, z3B, fc3_b, ohi, olo, out, t);
    }
}

// round 16
// speedup vs baseline: 1.7169x; 1.6393x over previous
#include <cuda_runtime.h>
#include <cuda_fp16.h>
#include <math.h>
#include <stdint.h>

#define BSZ  256
#define HDIM 1024
#define DDIM 256
#define TLEN 64
#define FC1N 1024
#define FC2N 512

// ============================ PTX helpers ====================================
__device__ __forceinline__ uint32_t smem_u32(const void* p) {
    uint32_t a;
    asm("{ .reg .u64 t; cvta.to.shared.u64 t, %1; cvt.u32.u64 %0, t; }" : "=r"(a) : "l"(p));
    return a;
}
__device__ __forceinline__ void ldmx4(uint32_t* r, uint32_t addr) {
    asm volatile("ldmatrix.sync.aligned.m8n8.x4.shared.b16 {%0,%1,%2,%3}, [%4];"
        : "=r"(r[0]), "=r"(r[1]), "=r"(r[2]), "=r"(r[3]) : "r"(addr));
}
__device__ __forceinline__ void mma_f16(float* d, const uint32_t* a, const uint32_t* b) {
    asm volatile("mma.sync.aligned.m16n8k16.row.col.f32.f16.f16.f32 "
        "{%0,%1,%2,%3}, {%4,%5,%6,%7}, {%8,%9}, {%0,%1,%2,%3};"
        : "+f"(d[0]), "+f"(d[1]), "+f"(d[2]), "+f"(d[3])
        : "r"(a[0]), "r"(a[1]), "r"(a[2]), "r"(a[3]), "r"(b[0]), "r"(b[1]));
}
__device__ __forceinline__ void cpasync16(uint32_t dst, const void* src) {
    asm volatile("cp.async.cg.shared.global [%0], [%1], 16;" :: "r"(dst), "l"(src));
}
#define CP_COMMIT asm volatile("cp.async.commit_group;" ::: "memory")
#define CP_WAIT0  asm volatile("cp.async.wait_group 0;" ::: "memory")

// ====================== persistent device scratch ============================
__device__ float g_h0f[BSZ * HDIM];
__device__ float g_h1f[BSZ * HDIM];
__device__ float g_giA[BSZ * 3 * HDIM], g_giB[BSZ * 3 * HDIM];
__device__ float g_ghA[BSZ * 3 * HDIM], g_ghB[BSZ * 3 * HDIM];
__device__ float g_z1A[BSZ * FC1N], g_z1B[BSZ * FC1N];
__device__ float g_z2A[BSZ * FC2N], g_z2B[BSZ * FC2N];
__device__ float g_z3A[BSZ * DDIM], g_z3B[BSZ * DDIM];
__device__ __half g_out_h[BSZ * DDIM];
__device__ __half g_h0_h [BSZ * HDIM];
__device__ __half g_h1_h [BSZ * HDIM];
__device__ __half g_z1_h [BSZ * FC1N];
__device__ __half g_z2_h [BSZ * FC2N];
__device__ __half g_wih0[3*HDIM*DDIM];
__device__ __half g_whh0[3*HDIM*HDIM];
__device__ __half g_wih1[3*HDIM*HDIM];
__device__ __half g_whh1[3*HDIM*HDIM];
__device__ __half g_fc1 [FC1N*HDIM];
__device__ __half g_fc2 [FC2N*FC1N];
__device__ __half g_fc3 [DDIM*FC2N];

// ============================ setup kernels ==================================
struct CvtJob { const float* src; __half* dst; int n; };
struct CvtJobs { CvtJob j[4]; int cnt; };

__global__ void cvt_multi(CvtJobs J) {
    for (int jb = 0; jb < J.cnt; jb++) {
        const float* __restrict__ src = J.j[jb].src;
        __half* __restrict__ dst = J.j[jb].dst;
        const int n = J.j[jb].n;
        for (int i = blockIdx.x * blockDim.x + threadIdx.x; i < n;
             i += gridDim.x * blockDim.x) {
            dst[i] = __float2half(src[i]);
        }
    }
}

__global__ void init_kernel(const float* __restrict__ hidden) {
    int i = blockIdx.x * blockDim.x + threadIdx.x;
    if (i < BSZ * HDIM) {
        float v0 = hidden[i];
        float v1 = hidden[BSZ * HDIM + i];
        g_h0f[i] = v0; g_h1f[i] = v1;
        g_h0_h[i] = __float2half(v0);
        g_h1_h[i] = __float2half(v1);
    }
    if (i < BSZ * DDIM) g_out_h[i] = __float2half(0.0f);
}

// ============================ elementwise kernels ============================
__device__ __forceinline__ float sigmoidf_(float x) { return 1.0f / (1.0f + expf(-x)); }

__global__ void gru_gate(const float4* __restrict__ giA, const float4* __restrict__ giB,
                         const float4* __restrict__ ghA, const float4* __restrict__ ghB,
                         const float4* __restrict__ bih, const float4* __restrict__ bhh,
                         float4* __restrict__ h, __half* __restrict__ hh)
{
    int idx = blockIdx.x * blockDim.x + threadIdx.x;   // B*H/4 threads
    int b = idx >> 8;
    int j = idx & 255;
    size_t o = (size_t)b * 768;
    float4 ir4, iz4, in4, hr4, hz4, hn4;
    {
        float4 a, c, bb;
        a = giA[o + j];       c = giB[o + j];       bb = bih[j];
        ir4 = make_float4(a.x+c.x+bb.x, a.y+c.y+bb.y, a.z+c.z+bb.z, a.w+c.w+bb.w);
        a = giA[o + 256 + j]; c = giB[o + 256 + j]; bb = bih[256 + j];
        iz4 = make_float4(a.x+c.x+bb.x, a.y+c.y+bb.y, a.z+c.z+bb.z, a.w+c.w+bb.w);
        a = giA[o + 512 + j]; c = giB[o + 512 + j]; bb = bih[512 + j];
        in4 = make_float4(a.x+c.x+bb.x, a.y+c.y+bb.y, a.z+c.z+bb.z, a.w+c.w+bb.w);
        a = ghA[o + j];       c = ghB[o + j];       bb = bhh[j];
        hr4 = make_float4(a.x+c.x+bb.x, a.y+c.y+bb.y, a.z+c.z+bb.z, a.w+c.w+bb.w);
        a = ghA[o + 256 + j]; c = ghB[o + 256 + j]; bb = bhh[256 + j];
        hz4 = make_float4(a.x+c.x+bb.x, a.y+c.y+bb.y, a.z+c.z+bb.z, a.w+c.w+bb.w);
        a = ghA[o + 512 + j]; c = ghB[o + 512 + j]; bb = bhh[512 + j];
        hn4 = make_float4(a.x+c.x+bb.x, a.y+c.y+bb.y, a.z+c.z+bb.z, a.w+c.w+bb.w);
    }
    float4 hv = h[idx];
    float irA[4] = {ir4.x, ir4.y, ir4.z, ir4.w}, izA[4] = {iz4.x, iz4.y, iz4.z, iz4.w};
    float inA[4] = {in4.x, in4.y, in4.z, in4.w};
    float hrA[4] = {hr4.x, hr4.y, hr4.z, hr4.w}, hzA[4] = {hz4.x, hz4.y, hz4.z, hz4.w};
    float hnA[4] = {hn4.x, hn4.y, hn4.z, hn4.w};
    float hvA[4] = {hv.x, hv.y, hv.z, hv.w};
    float out[4];
    #pragma unroll
    for (int k = 0; k < 4; k++) {
        float r = sigmoidf_(irA[k] + hrA[k]);
        float z = sigmoidf_(izA[k] + hzA[k]);
        float n = tanhf(inA[k] + r * hnA[k]);
        out[k] = (1.0f - z) * n + z * hvA[k];
    }
    h[idx] = make_float4(out[0], out[1], out[2], out[3]);
    int base = idx * 4;
    #pragma unroll
    for (int k = 0; k < 4; k++) hh[base + k] = __float2half(out[k]);
}

template <int N>
__global__ void ln_gelu(const float* __restrict__ xa, const float* __restrict__ xb,
                        const float* __restrict__ fcb,
                        const float* __restrict__ g, const float* __restrict__ b,
                        __half* __restrict__ dst)
{
    const int row = blockIdx.x;
    const int tid = threadIdx.x;
    __shared__ float sv[N];

    float s = 0.0f, s2 = 0.0f;
    #pragma unroll
    for (int j = tid; j < N; j += 256) {
        float v = xa[(size_t)row * N + j] + xb[(size_t)row * N + j] + fcb[j];
        sv[j] = v;
        s += v; s2 += v * v;
    }
    __shared__ float rs[256], rs2[256];
    rs[tid] = s; rs2[tid] = s2;
    __syncthreads();
    #pragma unroll
    for (int o = 128; o > 0; o >>= 1) {
        if (tid < o) { rs[tid] += rs[tid + o]; rs2[tid] += rs2[tid + o]; }
        __syncthreads();
    }
    float mu  = rs[0]  * (1.0f / N);
    float var = rs2[0] * (1.0f / N) - mu * mu;
    float inv = rsqrtf(var + 1e-5f);

    #pragma unroll
    for (int j = tid; j < N; j += 256) {
        float v = (sv[j] - mu) * inv * g[j] + b[j];
        float gv = 0.5f * v * (1.0f + erff(v * 0.70710678118654752f));
        dst[(size_t)row * N + j] = __float2half(gv);
    }
}

__global__ void softmax_store(const float* __restrict__ za, const float* __restrict__ zb,
                              const float* __restrict__ fcb,
                              __half* __restrict__ oh, float* __restrict__ dst, int t)
{
    const int b = blockIdx.x;
    const int j = threadIdx.x;     // 256 == DDIM
    float v = za[(size_t)b * DDIM + j] + zb[(size_t)b * DDIM + j] + fcb[j];

    __shared__ float red[256];
    red[j] = v;
    __syncthreads();
    #pragma unroll
    for (int o = 128; o > 0; o >>= 1) {
        if (j < o) red[j] = fmaxf(red[j], red[j + o]);
        __syncthreads();
    }
    float m = red[0];
    __syncthreads();
    float e = expf(v - m);
    red[j] = e;
    __syncthreads();
    #pragma unroll
    for (int o = 128; o > 0; o >>= 1) {
        if (j < o) red[j] += red[j + o];
        __syncthreads();
    }
    float p = e / red[0];
    oh[(size_t)b * DDIM + j] = __float2half(p);
    dst[((size_t)b * TLEN + t) * DDIM + j] = p;
}

// ======================= mma.sync fp16 batched GEMM ==========================
// Per-job: C[M, N] = A[M, kOff:kOff+kLen] @ B[N, kOff:kOff+kLen]^T
// fp16 operands, fp32 accumulate.  No bias (consumers add).
// blockIdx.z selects the job.  2-stage cp.async pipeline.
struct Job {
    const __half *A, *B;
    float* C;
    int K, kOff, kLen;
};
struct Jobs4 { Job j[4]; };

template <int BM, int BN, int WM, int WN>
__global__ __launch_bounds__((BM/WM)*(BN/WN)*32, ((BM/WM)*(BN/WN)*32) == 128 ? 4 : 2)
void gemm_batch(Jobs4 jobs, int N)
{
    constexpr int THREADS = (BM/WM)*(BN/WN)*32;
    constexpr int PITCH = 80;
    constexpr int A_SZ  = BM * PITCH;
    constexpr int B_SZ  = BN * PITCH;
    constexpr int STAGE = A_SZ + B_SZ;
    constexpr int WARPS_N = BN / WN;
    constexpr int MT  = WM / 16;
    constexpr int NT  = WN / 8;
    constexpr int NT2 = WN / 16;

    extern __shared__ char smem[];
    const uint32_t sb = smem_u32(smem);
    const int tid  = threadIdx.x;
    const int wid  = tid >> 5;
    const int lane = tid & 31;
    const int wm0 = (wid / WARPS_N) * WM;
    const int wn0 = (wid % WARPS_N) * WN;
    const int row0 = blockIdx.y * BM;
    const int col0 = blockIdx.x * BN;

    const Job jb = jobs.j[blockIdx.z];
    const int K  = jb.K;
    const int NC = jb.kLen >> 5;
    const __half* __restrict__ A = jb.A;
    const __half* __restrict__ B = jb.B;

    float acc[MT][NT][4] = {};

    auto copy_chunk = [&](int c, int buf) {
        const uint32_t base = sb + buf * STAGE;
        const int kb = jb.kOff + (c << 5);
        #pragma unroll
        for (int i = tid; i < BM * 4; i += THREADS) {
            int r = i >> 2, q = i & 3;
            cpasync16(base + r * PITCH + q * 16,
                      A + (size_t)(row0 + r) * K + kb + q * 8);
        }
        #pragma unroll
        for (int i = tid; i < BN * 4; i += THREADS) {
            int r = i >> 2, q = i & 3;
            cpasync16(base + A_SZ + r * PITCH + q * 16,
                      B + (size_t)(col0 + r) * K + kb + q * 8);
        }
    };

    copy_chunk(0, 0);
    CP_COMMIT;

    for (int c = 0; c < NC; c++) {
        CP_WAIT0;
        __syncthreads();
        if (c + 1 < NC) { copy_chunk(c + 1, (c + 1) & 1); CP_COMMIT; }

        const uint32_t aBase = sb + (c & 1) * STAGE;
        const uint32_t bBase = aBase + A_SZ;

        #pragma unroll
        for (int ks = 0; ks < 2; ks++) {
            uint32_t ah[MT][4];
            #pragma unroll
            for (int mt = 0; mt < MT; mt++) {
                uint32_t ad = aBase + (wm0 + mt * 16 + (lane & 15)) * PITCH
                            + ks * 32 + ((lane >> 4) << 4);
                ldmx4(ah[mt], ad);
            }
            #pragma unroll
            for (int n2 = 0; n2 < NT2; n2++) {
                uint32_t bh[4];
                int nr = wn0 + n2 * 16 + (lane & 7) + ((lane & 16) ? 8 : 0);
                uint32_t bd = bBase + nr * PITCH + ks * 32 + ((lane & 8) ? 16 : 0);
                ldmx4(bh, bd);
                #pragma unroll
                for (int mt = 0; mt < MT; mt++) {
                    mma_f16(acc[mt][n2 * 2 + 0], ah[mt], &bh[0]);
                    mma_f16(acc[mt][n2 * 2 + 1], ah[mt], &bh[2]);
                }
            }
        }
        __syncthreads();
    }

    float* __restrict__ C = jb.C;
    #pragma unroll
    for (int mt = 0; mt < MT; mt++) {
        int r0 = row0 + wm0 + mt * 16 + (lane >> 2);
        #pragma unroll
        for (int nt = 0; nt < NT; nt++) {
            int cc = col0 + wn0 + nt * 8 + (lane & 3) * 2;
            float2 v0 = { acc[mt][nt][0], acc[mt][nt][1] };
            float2 v1 = { acc[mt][nt][2], acc[mt][nt][3] };
            *(float2*)(C + (size_t)r0 * N + cc)       = v0;
            *(float2*)(C + (size_t)(r0 + 8) * N + cc) = v1;
        }
    }
}

// ============================ host side ======================================
// big:   128x64 CTA tile, 4 warps (128 thr), warp tile 32x64, 2-stage
// small: 64x64 CTA tile, 8 warps (256 thr), warp tile 16x32, 2-stage
#define SMEM_BIG   (2 * (128 * 80 + 64 * 80))   // 30720
#define SMEM_SMALL (2 * (64 * 80 + 64 * 80))    // 20480

extern "C" void kernel_launch(void* const* d_in, const int* in_sizes, int n_in,
                              void* d_out, int out_size)
{
    const float* hidden = (const float*)d_in[0];
    const float* W_ih0  = (const float*)d_in[1];
    const float* W_hh0  = (const float*)d_in[2];
    const float* b_ih0  = (const float*)d_in[3];
    const float* b_hh0  = (const float*)d_in[4];
    const float* W_ih1  = (const float*)d_in[5];
    const float* W_hh1  = (const float*)d_in[6];
    const float* b_ih1  = (const float*)d_in[7];
    const float* b_hh1  = (const float*)d_in[8];
    const float* fc1_w  = (const float*)d_in[9];
    const float* fc1_b  = (const float*)d_in[10];
    const float* ln1_g  = (const float*)d_in[11];
    const float* ln1_b  = (const float*)d_in[12];
    const float* fc2_w  = (const float*)d_in[13];
    const float* fc2_b  = (const float*)d_in[14];
    const float* ln2_g  = (const float*)d_in[15];
    const float* ln2_b  = (const float*)d_in[16];
    const float* fc3_w  = (const float*)d_in[17];
    const float* fc3_b  = (const float*)d_in[18];
    float* out = (float*)d_out;

    cudaFuncSetAttribute((const void*)gemm_batch<128, 64, 32, 64>,
                         cudaFuncAttributeMaxDynamicSharedMemorySize, SMEM_BIG);
    cudaFuncSetAttribute((const void*)gemm_batch<64, 64, 16, 32>,
                         cudaFuncAttributeMaxDynamicSharedMemorySize, SMEM_SMALL);

    float *giA, *giB, *ghA, *ghB, *z1A, *z1B, *z2A, *z2B, *z3A, *z3B, *h0f, *h1f;
    __half *oh, *h0h, *h1h, *z1h, *z2h;
    __half *wih0, *whh0, *wih1, *whh1, *f1, *f2, *f3;
    cudaGetSymbolAddress((void**)&h0f, g_h0f);  cudaGetSymbolAddress((void**)&h1f, g_h1f);
    cudaGetSymbolAddress((void**)&giA, g_giA);  cudaGetSymbolAddress((void**)&giB, g_giB);
    cudaGetSymbolAddress((void**)&ghA, g_ghA);  cudaGetSymbolAddress((void**)&ghB, g_ghB);
    cudaGetSymbolAddress((void**)&z1A, g_z1A);  cudaGetSymbolAddress((void**)&z1B, g_z1B);
    cudaGetSymbolAddress((void**)&z2A, g_z2A);  cudaGetSymbolAddress((void**)&z2B, g_z2B);
    cudaGetSymbolAddress((void**)&z3A, g_z3A);  cudaGetSymbolAddress((void**)&z3B, g_z3B);
    cudaGetSymbolAddress((void**)&oh,  g_out_h);
    cudaGetSymbolAddress((void**)&h0h, g_h0_h); cudaGetSymbolAddress((void**)&h1h, g_h1_h);
    cudaGetSymbolAddress((void**)&z1h, g_z1_h); cudaGetSymbolAddress((void**)&z2h, g_z2_h);
    cudaGetSymbolAddress((void**)&wih0, g_wih0); cudaGetSymbolAddress((void**)&whh0, g_whh0);
    cudaGetSymbolAddress((void**)&wih1, g_wih1); cudaGetSymbolAddress((void**)&whh1, g_whh1);
    cudaGetSymbolAddress((void**)&f1, g_fc1); cudaGetSymbolAddress((void**)&f2, g_fc2);
    cudaGetSymbolAddress((void**)&f3, g_fc3);

    // setup = exactly 3 launches, so ncu (-s 5 -c 1) captures the 6th launch:
    // [1] cvtA  [2] cvtB  [3] init  [4] L0-gemm  [5] gate0  [6] L1-gemm <- profiled
    {
        CvtJobs JA;
        JA.j[0] = { W_ih0, wih0, 3 * HDIM * DDIM };
        JA.j[1] = { W_hh0, whh0, 3 * HDIM * HDIM };
        JA.j[2] = { W_ih1, wih1, 3 * HDIM * HDIM };
        JA.cnt = 3;
        cvt_multi<<<2048, 256>>>(JA);
        CvtJobs JB;
        JB.j[0] = { W_hh1, whh1, 3 * HDIM * HDIM };
        JB.j[1] = { fc1_w, f1, FC1N * HDIM };
        JB.j[2] = { fc2_w, f2, FC2N * FC1N };
        JB.j[3] = { fc3_w, f3, DDIM * FC2N };
        JB.cnt = 4;
        cvt_multi<<<2048, 256>>>(JB);
    }
    init_kernel<<<(BSZ * HDIM + 255) / 256, 256>>>(hidden);

    for (int t = 0; t < TLEN; t++) {
        // ---- GRU layer 0: 4 sub-jobs in one launch (384 CTAs) ----
        {
            Jobs4 J;
            J.j[0] = { oh,  wih0, giA, DDIM, 0,   128 };
            J.j[1] = { oh,  wih0, giB, DDIM, 128, 128 };
            J.j[2] = { h0h, whh0, ghA, HDIM, 0,   512 };
            J.j[3] = { h0h, whh0, ghB, HDIM, 512, 512 };
            dim3 grid(3 * HDIM / 64, BSZ / 128, 4);
            gemm_batch<128, 64, 32, 64><<<grid, 128, SMEM_BIG>>>(J, 3 * HDIM);
        }
        gru_gate<<<(BSZ * HDIM / 4) / 256, 256>>>(
            (const float4*)giA, (const float4*)giB, (const float4*)ghA, (const float4*)ghB,
            (const float4*)b_ih0, (const float4*)b_hh0, (float4*)h0f, h0h);

        // ---- GRU layer 1: 4 sub-jobs in one launch (384 CTAs) ----
        {
            Jobs4 J;
            J.j[0] = { h0h, wih1, giA, HDIM, 0,   512 };
            J.j[1] = { h0h, wih1, giB, HDIM, 512, 512 };
            J.j[2] = { h1h, whh1, ghA, HDIM, 0,   512 };
            J.j[3] = { h1h, whh1, ghB, HDIM, 512, 512 };
            dim3 grid(3 * HDIM / 64, BSZ / 128, 4);
            gemm_batch<128, 64, 32, 64><<<grid, 128, SMEM_BIG>>>(J, 3 * HDIM);
        }
        gru_gate<<<(BSZ * HDIM / 4) / 256, 256>>>(
            (const float4*)giA, (const float4*)giB, (const float4*)ghA, (const float4*)ghB,
            (const float4*)b_ih1, (const float4*)b_hh1, (float4*)h1f, h1h);

        // ---- FC head (split-K=2, BM=64 tiles) ----
        {
            Jobs4 J;
            J.j[0] = { h1h, f1, z1A, HDIM, 0,   512 };
            J.j[1] = { h1h, f1, z1B, HDIM, 512, 512 };
            dim3 grid(FC1N / 64, BSZ / 64, 2);
            gemm_batch<64, 64, 16, 32><<<grid, 256, SMEM_SMALL>>>(J, FC1N);
        }
        ln_gelu<FC1N><<<BSZ, 256>>>(z1A, z1B, fc1_b, ln1_g, ln1_b, z1h);
        {
            Jobs4 J;
            J.j[0] = { z1h, f2, z2A, FC1N, 0,   512 };
            J.j[1] = { z1h, f2, z2B, FC1N, 512, 512 };
            dim3 grid(FC2N / 64, BSZ / 64, 2);
            gemm_batch<64, 64, 16, 32><<<grid, 256, SMEM_SMALL>>>(J, FC2N);
        }
        ln_gelu<FC2N><<<BSZ, 256>>>(z2A, z2B, fc2_b, ln2_g, ln2_b, z2h);
        {
            Jobs4 J;
            J.j[0] = { z2h, f3, z3A, FC2N, 0,   256 };
            J.j[1] = { z2h, f3, z3B, FC2N, 256, 256 };
            dim3 grid(DDIM / 64, BSZ / 64, 2);
            gemm_batch<64, 64, 16, 32><<<grid, 256, SMEM_SMALL>>>(J, DDIM);
        }
        softmax_store<<<BSZ, DDIM>>>(z3A, z3B, fc3_b, oh, out, t);
    }
}